// round 11
// baseline (speedup 1.0000x reference)
#include <cuda_runtime.h>
#include <math_constants.h>

// Problem constants
#define Bb 2
#define Ss 4096
#define Hh 8
#define HDv 512   // H*D (D=64)

typedef unsigned long long ull;
typedef unsigned int u32;

// Scratch (device globals; no allocation allowed)
__device__ float Qg[Bb * Ss * HDv];
__device__ float Kg[Bb * Ss * HDv];
__device__ float Vg[Bb * Ss * HDv];
__device__ float Og[Bb * Ss * HDv];

#define MWORDS (Bb * Hh * Ss * (Ss / 32))   // 8,388,608 u32 = 33.5 MB
__device__ u32 Mpg[MWORDS];

// ---- helpers --------------------------------------------------------------
__device__ __forceinline__ u32 to_tf32(float f) {
    u32 r; asm("cvt.rna.tf32.f32 %0, %1;" : "=r"(r) : "f"(f)); return r;
}
__device__ __forceinline__ void mma_tf32(
    float& d0, float& d1, float& d2, float& d3,
    u32 a0, u32 a1, u32 a2, u32 a3, u32 b0, u32 b1)
{
    asm("mma.sync.aligned.m16n8k8.row.col.f32.tf32.tf32.f32 "
        "{%0,%1,%2,%3}, {%4,%5,%6,%7}, {%8,%9}, {%0,%1,%2,%3};"
        : "+f"(d0), "+f"(d1), "+f"(d2), "+f"(d3)
        : "r"(a0), "r"(a1), "r"(a2), "r"(a3), "r"(b0), "r"(b1));
}
__device__ __forceinline__ void cpa16(u32 dst, const void* src) {
    asm volatile("cp.async.cg.shared.global [%0], [%1], 16;"
                 :: "r"(dst), "l"(src) : "memory");
}
__device__ __forceinline__ void cpa_commit() {
    asm volatile("cp.async.commit_group;" ::: "memory");
}
__device__ __forceinline__ void cpa_wait1() {
    asm volatile("cp.async.wait_group 1;" ::: "memory");
}

// ---------------------------------------------------------------------------
// GEMM core (tf32, CTA 128x128, BK=32, 256 threads, warp m32 x n64).
// Shared by QKV-fused kernel and the Wo kernel.
// ---------------------------------------------------------------------------
#define LDA 36
#define LDB 136

template <bool ROUND_OUT>
__device__ __forceinline__ void gemm_tf32_body(
    const float* __restrict__ A, const float* __restrict__ Bw,
    float* __restrict__ C, u32* As, u32* Bs)
{
    const int tid  = threadIdx.x;
    const int lane = tid & 31;
    const int w    = tid >> 5;
    const int g    = lane >> 2;
    const int c    = lane & 3;
    const int wm   = w & 3;
    const int wn   = w >> 2;
    const int bn = blockIdx.x * 128;
    const int bm = blockIdx.y * 128;

    const int arow = tid >> 1;
    const int akg  = (tid & 1) * 16;
    const int brow = tid >> 3;
    const int bcg  = (tid & 7) * 16;

    float acc[2][8][4];
#pragma unroll
    for (int mt = 0; mt < 2; ++mt)
#pragma unroll
        for (int nt = 0; nt < 8; ++nt)
#pragma unroll
            for (int j = 0; j < 4; ++j) acc[mt][nt][j] = 0.f;

    for (int k0 = 0; k0 < 512; k0 += 32) {
        {
            const float* Ap = A + (size_t)(bm + arow) * 512 + k0 + akg;
#pragma unroll
            for (int i = 0; i < 4; ++i) {
                float4 v = *(const float4*)(Ap + 4 * i);
                *(uint4*)&As[arow * LDA + akg + 4 * i] =
                    make_uint4(to_tf32(v.x), to_tf32(v.y), to_tf32(v.z), to_tf32(v.w));
            }
        }
        {
            const float* Bp = Bw + (size_t)(k0 + brow) * 512 + bn + bcg;
#pragma unroll
            for (int i = 0; i < 4; ++i) {
                float4 v = *(const float4*)(Bp + 4 * i);
                *(uint4*)&Bs[brow * LDB + bcg + 4 * i] =
                    make_uint4(to_tf32(v.x), to_tf32(v.y), to_tf32(v.z), to_tf32(v.w));
            }
        }
        __syncthreads();

#pragma unroll
        for (int ks = 0; ks < 4; ++ks) {
            u32 a[2][4];
#pragma unroll
            for (int mt = 0; mt < 2; ++mt) {
                int base = (32 * wm + 16 * mt + g) * LDA + ks * 8 + c;
                a[mt][0] = As[base];
                a[mt][1] = As[base + 8 * LDA];
                a[mt][2] = As[base + 4];
                a[mt][3] = As[base + 8 * LDA + 4];
            }
#pragma unroll
            for (int nt = 0; nt < 8; ++nt) {
                u32 b0 = Bs[(ks * 8 + c)     * LDB + 64 * wn + nt * 8 + g];
                u32 b1 = Bs[(ks * 8 + c + 4) * LDB + 64 * wn + nt * 8 + g];
#pragma unroll
                for (int mt = 0; mt < 2; ++mt)
                    mma_tf32(acc[mt][nt][0], acc[mt][nt][1], acc[mt][nt][2], acc[mt][nt][3],
                             a[mt][0], a[mt][1], a[mt][2], a[mt][3], b0, b1);
            }
        }
        __syncthreads();
    }

#pragma unroll
    for (int mt = 0; mt < 2; ++mt) {
        float* Cp0 = C + (size_t)(bm + 32 * wm + 16 * mt + g) * 512 + bn + 64 * wn;
        float* Cp1 = Cp0 + (size_t)8 * 512;
#pragma unroll
        for (int nt = 0; nt < 8; ++nt) {
            if (ROUND_OUT) {
                *(uint2*)(Cp0 + nt * 8 + 2 * c) =
                    make_uint2(to_tf32(acc[mt][nt][0]), to_tf32(acc[mt][nt][1]));
                *(uint2*)(Cp1 + nt * 8 + 2 * c) =
                    make_uint2(to_tf32(acc[mt][nt][2]), to_tf32(acc[mt][nt][3]));
            } else {
                *(float2*)(Cp0 + nt * 8 + 2 * c) =
                    make_float2(acc[mt][nt][0], acc[mt][nt][1]);
                *(float2*)(Cp1 + nt * 8 + 2 * c) =
                    make_float2(acc[mt][nt][2], acc[mt][nt][3]);
            }
        }
    }
}

// ---------------------------------------------------------------------------
// Fused QKV projections + mask bit-pack.
// grid (4, 64, 4): z=0,1,2 -> tf32 GEMM (tf32-rounded outputs);
//                  z=3     -> mask pack (DRAM-bound; overlaps the GEMMs).
// ---------------------------------------------------------------------------
__global__ __launch_bounds__(256) void gemm_qkv_pack(
    const float* __restrict__ A0, const float* __restrict__ A1,
    const float* __restrict__ A2,
    const float* __restrict__ W0, const float* __restrict__ W1,
    const float* __restrict__ W2,
    float* __restrict__ C0, float* __restrict__ C1, float* __restrict__ C2,
    const int* __restrict__ Mask)
{
    __shared__ u32 As[128 * LDA];
    __shared__ u32 Bs[32 * LDB];

    if (blockIdx.z == 3) {
        // mask pack: 256 blocks x 8 warps = 2048 warps
        const int lane = threadIdx.x & 31;
        const int bid  = blockIdx.x + 4 * blockIdx.y;     // 0..255
        const int wid  = bid * 8 + (threadIdx.x >> 5);    // 0..2047
        const int nw   = 2048;
        for (int w0 = wid; w0 < MWORDS; w0 += 4 * nw) {
            int w1 = w0 + nw, w2 = w0 + 2 * nw, w3 = w0 + 3 * nw;
            int v0 = Mask[(size_t)w0 * 32 + lane];
            int v1 = (w1 < MWORDS) ? Mask[(size_t)w1 * 32 + lane] : 0;
            int v2 = (w2 < MWORDS) ? Mask[(size_t)w2 * 32 + lane] : 0;
            int v3 = (w3 < MWORDS) ? Mask[(size_t)w3 * 32 + lane] : 0;
            u32 b0 = __ballot_sync(0xffffffffu, v0 != 0);
            u32 b1 = __ballot_sync(0xffffffffu, v1 != 0);
            u32 b2 = __ballot_sync(0xffffffffu, v2 != 0);
            u32 b3 = __ballot_sync(0xffffffffu, v3 != 0);
            if (lane == 0) {
                Mpg[w0] = b0;
                if (w1 < MWORDS) Mpg[w1] = b1;
                if (w2 < MWORDS) Mpg[w2] = b2;
                if (w3 < MWORDS) Mpg[w3] = b3;
            }
        }
        return;
    }

    const float* A; const float* Bw; float* C;
    if (blockIdx.z == 0)      { A = A0; Bw = W0; C = C0; }
    else if (blockIdx.z == 1) { A = A1; Bw = W1; C = C1; }
    else                      { A = A2; Bw = W2; C = C2; }
    gemm_tf32_body<true>(A, Bw, C, As, Bs);
}

// ---------------------------------------------------------------------------
// Wo projection: tf32 GEMM, fp32 output.
// ---------------------------------------------------------------------------
__global__ __launch_bounds__(256) void gemm_wo_tf32(
    const float* __restrict__ A, const float* __restrict__ Bw,
    float* __restrict__ C)
{
    __shared__ u32 As[128 * LDA];
    __shared__ u32 Bs[32 * LDB];
    gemm_tf32_body<false>(A, Bw, C, As, Bs);
}

// ---------------------------------------------------------------------------
// Flash attention v11:
//  - tf32 mma, Bq=128, 256 threads = 8 warps, warp tile m16 x n64
//  - Q FRAGMENTS IN REGISTERS (loaded once; no Q smem, no Q LDS in loop)
//  - permuted K (slot(k)=((k&3)<<1)|(k>>2) in 8-groups): S accumulator regs
//    ARE the PV A-fragments -> zero shuffles; V natural [k][d]
//  - mask from pre-packed bits (Mpg): 4 u32 loads per thread per iter
//  - cp.async double-buffered K/V
// smem: 2*K[64][68] + 2*V[64][72] = 71680 B -> 2 CTAs/SM (reg-bound), 16 warps.
// ---------------------------------------------------------------------------
#define LDK 68
#define LDV 72
#define KBW  (64 * LDK)
#define VBW  (64 * LDV)
#define KOFF 0
#define VOFF (2 * KBW)
#define FSMEM ((2 * KBW + 2 * VBW) * 4)   // 71680

__global__ void __launch_bounds__(256, 2) flash_attn(
    const float* __restrict__ Q, const float* __restrict__ K,
    const float* __restrict__ V, float* __restrict__ O)
{
    extern __shared__ u32 dsm[];
    const u32 sbase = (u32)__cvta_generic_to_shared(dsm);

    const int tid  = threadIdx.x;
    const int lane = tid & 31;
    const int w    = tid >> 5;       // warp 0..7 -> q rows [16w, 16w+16)
    const int g    = lane >> 2;
    const int c    = lane & 3;
    const int q0 = blockIdx.x * 128;
    const int h  = blockIdx.y;
    const int b  = blockIdx.z;

    // K/V coop load: 64 rows, 4 threads per row (16 floats each)
    const int r2 = tid >> 2;
    const int qt = (tid & 3) * 16;
    const int prow = (r2 & 56) | (((r2 & 3) << 1) | ((r2 & 7) >> 2));

    const float* ksrc0 = K + ((size_t)(b * Ss + r2)) * HDv + h * 64 + qt;
    const float* vsrc0 = V + ((size_t)(b * Ss + r2)) * HDv + h * 64 + qt;
    const u32 kdst0 = sbase + (KOFF + prow * LDK + qt) * 4;
    const u32 vdst0 = sbase + (VOFF + r2 * LDV + qt) * 4;

    // prologue: issue K/V tile 0 into buffer 0
#pragma unroll
    for (int j = 0; j < 4; ++j) {
        cpa16(kdst0 + 16 * j, ksrc0 + 4 * j);
        cpa16(vdst0 + 16 * j, vsrc0 + 4 * j);
    }
    cpa_commit();

    // Q fragments -> registers (Q already tf32-valued from projection epilogue)
    u32 qf[8][4];
    {
        const u32* q0p = (const u32*)(Q + (size_t)(b * Ss + q0 + 16 * w + g) * HDv + h * 64);
        const u32* q1p = q0p + 8 * HDv;
#pragma unroll
        for (int ks = 0; ks < 8; ++ks) {
            qf[ks][0] = q0p[ks * 8 + c];
            qf[ks][1] = q1p[ks * 8 + c];
            qf[ks][2] = q0p[ks * 8 + c + 4];
            qf[ks][3] = q1p[ks * 8 + c + 4];
        }
    }

    float m_[2], l_[2];
    float o[8][4];
    m_[0] = m_[1] = -CUDART_INF_F;
    l_[0] = l_[1] = 0.f;
#pragma unroll
    for (int nt = 0; nt < 8; ++nt)
#pragma unroll
        for (int j = 0; j < 4; ++j) o[nt][j] = 0.f;

    // packed-mask word bases (Ss/32 = 128 words per q-row)
    const size_t mw0 = ((size_t)((b * Hh + h) * Ss + q0 + 16 * w + g)) * 128;
    const size_t mw1 = mw0 + (size_t)8 * 128;

    for (int it = 0; it < Ss / 64; ++it) {
        const int buf = it & 1;
        __syncthreads();   // prev compute on buf^1 done -> safe to overwrite

        // mask words for this tile
        u32 mwa0 = Mpg[mw0 + it * 2], mwa1 = Mpg[mw0 + it * 2 + 1];
        u32 mwb0 = Mpg[mw1 + it * 2], mwb1 = Mpg[mw1 + it * 2 + 1];

        // issue next K/V tile into the other buffer
        if (it + 1 < Ss / 64) {
            const float* kp = ksrc0 + (size_t)(it + 1) * 64 * HDv;
            const float* vp = vsrc0 + (size_t)(it + 1) * 64 * HDv;
            const u32 kd = kdst0 + (buf ^ 1) * KBW * 4;
            const u32 vd = vdst0 + (buf ^ 1) * VBW * 4;
#pragma unroll
            for (int j = 0; j < 4; ++j) {
                cpa16(kd + 16 * j, kp + 4 * j);
                cpa16(vd + 16 * j, vp + 4 * j);
            }
        }
        cpa_commit();
        cpa_wait1();       // current tile arrived
        __syncthreads();   // visible to all warps

        const u32* Kc = dsm + KOFF + buf * KBW;
        const u32* Vc = dsm + VOFF + buf * VBW;

        // ---- S = Q K^T (K columns in permuted slot order) ----
        float s[8][4];
#pragma unroll
        for (int nt = 0; nt < 8; ++nt)
#pragma unroll
            for (int j = 0; j < 4; ++j) s[nt][j] = 0.f;

#pragma unroll
        for (int ks = 0; ks < 8; ++ks) {
#pragma unroll
            for (int nt = 0; nt < 8; ++nt) {
                u32 b0 = Kc[(nt * 8 + g) * LDK + ks * 8 + c];
                u32 b1 = Kc[(nt * 8 + g) * LDK + ks * 8 + c + 4];
                mma_tf32(s[nt][0], s[nt][1], s[nt][2], s[nt][3],
                         qf[ks][0], qf[ks][1], qf[ks][2], qf[ks][3], b0, b1);
            }
        }

        // ---- online softmax; P (tf32-rounded) stays in s[] ----
#pragma unroll
        for (int sb = 0; sb < 2; ++sb) {
            const int j0 = 2 * sb, j1 = 2 * sb + 1;
            const u32 wa = sb ? mwb0 : mwa0;   // cols [it*64, +32)
            const u32 wb = sb ? mwb1 : mwa1;   // cols [it*64+32, +32)
            float mt_ = -CUDART_INF_F;
#pragma unroll
            for (int nt = 0; nt < 8; ++nt) {
                const u32 word = (nt < 4) ? wa : wb;
                const int sh = ((nt & 3) * 8) + c;
                s[nt][j0] = ((word >> sh) & 1u)       ? -1e10f : s[nt][j0] * 0.125f;
                s[nt][j1] = ((word >> (sh + 4)) & 1u) ? -1e10f : s[nt][j1] * 0.125f;
                mt_ = fmaxf(mt_, fmaxf(s[nt][j0], s[nt][j1]));
            }
            mt_ = fmaxf(mt_, __shfl_xor_sync(0xffffffffu, mt_, 1));
            mt_ = fmaxf(mt_, __shfl_xor_sync(0xffffffffu, mt_, 2));
            float mnew = fmaxf(m_[sb], mt_);
            float corr = __expf(m_[sb] - mnew);
            m_[sb] = mnew;
            float rs = 0.f;
#pragma unroll
            for (int nt = 0; nt < 8; ++nt) {
                float p0 = __uint_as_float(to_tf32(__expf(s[nt][j0] - mnew)));
                float p1 = __uint_as_float(to_tf32(__expf(s[nt][j1] - mnew)));
                rs += p0 + p1;
                s[nt][j0] = p0;
                s[nt][j1] = p1;
                o[nt][j0] *= corr;
                o[nt][j1] *= corr;
            }
            rs += __shfl_xor_sync(0xffffffffu, rs, 1);
            rs += __shfl_xor_sync(0xffffffffu, rs, 2);
            l_[sb] = l_[sb] * corr + rs;
        }

        // ---- O += P V : A-fragments straight from s[] ----
#pragma unroll
        for (int kc = 0; kc < 8; ++kc) {
#pragma unroll
            for (int nt = 0; nt < 8; ++nt) {
                u32 b0 = Vc[(kc * 8 + c)     * LDV + nt * 8 + g];
                u32 b1 = Vc[(kc * 8 + c + 4) * LDV + nt * 8 + g];
                mma_tf32(o[nt][0], o[nt][1], o[nt][2], o[nt][3],
                         __float_as_uint(s[kc][0]), __float_as_uint(s[kc][2]),
                         __float_as_uint(s[kc][1]), __float_as_uint(s[kc][3]),
                         b0, b1);
            }
        }
    }

    // normalize + write
    const float inv0 = 1.f / l_[0];
    const float inv1 = 1.f / l_[1];
    float* op0 = O + (size_t)(b * Ss + q0 + 16 * w + g) * HDv + h * 64;
    float* op1 = op0 + (size_t)8 * HDv;
#pragma unroll
    for (int nt = 0; nt < 8; ++nt) {
        *(float2*)(op0 + nt * 8 + 2 * c) = make_float2(o[nt][0] * inv0, o[nt][1] * inv0);
        *(float2*)(op1 + nt * 8 + 2 * c) = make_float2(o[nt][2] * inv1, o[nt][3] * inv1);
    }
}

// ---------------------------------------------------------------------------
// Launch
// ---------------------------------------------------------------------------
extern "C" void kernel_launch(void* const* d_in, const int* in_sizes, int n_in,
                              void* d_out, int out_size)
{
    (void)in_sizes; (void)n_in; (void)out_size;
    const float* queries = (const float*)d_in[0];
    const float* keys    = (const float*)d_in[1];
    const float* values  = (const float*)d_in[2];
    const int*   mask    = (const int*)d_in[3];
    const float* Wq = (const float*)d_in[4];
    const float* Wk = (const float*)d_in[5];
    const float* Wv = (const float*)d_in[6];
    const float* Wo = (const float*)d_in[7];

    void *qp, *kp, *vp, *op;
    cudaGetSymbolAddress(&qp, Qg);
    cudaGetSymbolAddress(&kp, Kg);
    cudaGetSymbolAddress(&vp, Vg);
    cudaGetSymbolAddress(&op, Og);

    cudaFuncSetAttribute(flash_attn,
                         cudaFuncAttributeMaxDynamicSharedMemorySize, FSMEM);

    // fused QKV projections + mask pack (z=3 packs; overlaps the GEMMs)
    gemm_qkv_pack<<<dim3(4, 64, 4), 256>>>(queries, keys, values, Wq, Wk, Wv,
                                           (float*)qp, (float*)kp, (float*)vp,
                                           mask);

    flash_attn<<<dim3(Ss / 128, Hh, Bb), 256, FSMEM>>>(
        (const float*)qp, (const float*)kp, (const float*)vp, (float*)op);

    gemm_wo_tf32<<<dim3(4, 64), 256>>>((const float*)op, Wo, (float*)d_out);
}

// round 12
// speedup vs baseline: 1.0182x; 1.0182x over previous
#include <cuda_runtime.h>
#include <math_constants.h>

// Problem constants
#define Bb 2
#define Ss 4096
#define Hh 8
#define HDv 512   // H*D (D=64)

typedef unsigned long long ull;
typedef unsigned int u32;

// Scratch (device globals; no allocation allowed)
__device__ float Qg[Bb * Ss * HDv];
__device__ float Kg[Bb * Ss * HDv];
__device__ float Vg[Bb * Ss * HDv];
__device__ float Og[Bb * Ss * HDv];

#define MWORDS (Bb * Hh * Ss * (Ss / 32))   // 8,388,608 u32 = 33.5 MB
__device__ u32 Mpg[MWORDS];

// ---- helpers --------------------------------------------------------------
__device__ __forceinline__ u32 to_tf32(float f) {
    u32 r; asm("cvt.rna.tf32.f32 %0, %1;" : "=r"(r) : "f"(f)); return r;
}
__device__ __forceinline__ void mma_tf32(
    float& d0, float& d1, float& d2, float& d3,
    u32 a0, u32 a1, u32 a2, u32 a3, u32 b0, u32 b1)
{
    asm("mma.sync.aligned.m16n8k8.row.col.f32.tf32.tf32.f32 "
        "{%0,%1,%2,%3}, {%4,%5,%6,%7}, {%8,%9}, {%0,%1,%2,%3};"
        : "+f"(d0), "+f"(d1), "+f"(d2), "+f"(d3)
        : "r"(a0), "r"(a1), "r"(a2), "r"(a3), "r"(b0), "r"(b1));
}
__device__ __forceinline__ void cpa16(u32 dst, const void* src) {
    asm volatile("cp.async.cg.shared.global [%0], [%1], 16;"
                 :: "r"(dst), "l"(src) : "memory");
}
__device__ __forceinline__ void cpa_commit() {
    asm volatile("cp.async.commit_group;" ::: "memory");
}
__device__ __forceinline__ void cpa_wait1() {
    asm volatile("cp.async.wait_group 1;" ::: "memory");
}

// ---------------------------------------------------------------------------
// GEMM core (tf32, CTA 128x128, BK=32, 256 threads, warp m32 x n64).
// ---------------------------------------------------------------------------
#define LDA 36
#define LDB 136

template <bool ROUND_OUT>
__device__ __forceinline__ void gemm_tf32_body(
    const float* __restrict__ A, const float* __restrict__ Bw,
    float* __restrict__ C, u32* As, u32* Bs)
{
    const int tid  = threadIdx.x;
    const int lane = tid & 31;
    const int w    = tid >> 5;
    const int g    = lane >> 2;
    const int c    = lane & 3;
    const int wm   = w & 3;
    const int wn   = w >> 2;
    const int bn = blockIdx.x * 128;
    const int bm = blockIdx.y * 128;

    const int arow = tid >> 1;
    const int akg  = (tid & 1) * 16;
    const int brow = tid >> 3;
    const int bcg  = (tid & 7) * 16;

    float acc[2][8][4];
#pragma unroll
    for (int mt = 0; mt < 2; ++mt)
#pragma unroll
        for (int nt = 0; nt < 8; ++nt)
#pragma unroll
            for (int j = 0; j < 4; ++j) acc[mt][nt][j] = 0.f;

    for (int k0 = 0; k0 < 512; k0 += 32) {
        {
            const float* Ap = A + (size_t)(bm + arow) * 512 + k0 + akg;
#pragma unroll
            for (int i = 0; i < 4; ++i) {
                float4 v = *(const float4*)(Ap + 4 * i);
                *(uint4*)&As[arow * LDA + akg + 4 * i] =
                    make_uint4(to_tf32(v.x), to_tf32(v.y), to_tf32(v.z), to_tf32(v.w));
            }
        }
        {
            const float* Bp = Bw + (size_t)(k0 + brow) * 512 + bn + bcg;
#pragma unroll
            for (int i = 0; i < 4; ++i) {
                float4 v = *(const float4*)(Bp + 4 * i);
                *(uint4*)&Bs[brow * LDB + bcg + 4 * i] =
                    make_uint4(to_tf32(v.x), to_tf32(v.y), to_tf32(v.z), to_tf32(v.w));
            }
        }
        __syncthreads();

#pragma unroll
        for (int ks = 0; ks < 4; ++ks) {
            u32 a[2][4];
#pragma unroll
            for (int mt = 0; mt < 2; ++mt) {
                int base = (32 * wm + 16 * mt + g) * LDA + ks * 8 + c;
                a[mt][0] = As[base];
                a[mt][1] = As[base + 8 * LDA];
                a[mt][2] = As[base + 4];
                a[mt][3] = As[base + 8 * LDA + 4];
            }
#pragma unroll
            for (int nt = 0; nt < 8; ++nt) {
                u32 b0 = Bs[(ks * 8 + c)     * LDB + 64 * wn + nt * 8 + g];
                u32 b1 = Bs[(ks * 8 + c + 4) * LDB + 64 * wn + nt * 8 + g];
#pragma unroll
                for (int mt = 0; mt < 2; ++mt)
                    mma_tf32(acc[mt][nt][0], acc[mt][nt][1], acc[mt][nt][2], acc[mt][nt][3],
                             a[mt][0], a[mt][1], a[mt][2], a[mt][3], b0, b1);
            }
        }
        __syncthreads();
    }

#pragma unroll
    for (int mt = 0; mt < 2; ++mt) {
        float* Cp0 = C + (size_t)(bm + 32 * wm + 16 * mt + g) * 512 + bn + 64 * wn;
        float* Cp1 = Cp0 + (size_t)8 * 512;
#pragma unroll
        for (int nt = 0; nt < 8; ++nt) {
            if (ROUND_OUT) {
                *(uint2*)(Cp0 + nt * 8 + 2 * c) =
                    make_uint2(to_tf32(acc[mt][nt][0]), to_tf32(acc[mt][nt][1]));
                *(uint2*)(Cp1 + nt * 8 + 2 * c) =
                    make_uint2(to_tf32(acc[mt][nt][2]), to_tf32(acc[mt][nt][3]));
            } else {
                *(float2*)(Cp0 + nt * 8 + 2 * c) =
                    make_float2(acc[mt][nt][0], acc[mt][nt][1]);
                *(float2*)(Cp1 + nt * 8 + 2 * c) =
                    make_float2(acc[mt][nt][2], acc[mt][nt][3]);
            }
        }
    }
}

// ---------------------------------------------------------------------------
// Fused QKV projections + mask bit-pack.
// grid (4, 64, 7): z=0,1,2 -> tf32 GEMMs (tf32-rounded outputs);
//                  z=3..6  -> mask pack with FULL parallelism
//                             (4*256 = 1024 blocks = 8192 warps, matching the
//                              proven standalone packer's DRAM rate).
// ---------------------------------------------------------------------------
__global__ __launch_bounds__(256) void gemm_qkv_pack(
    const float* __restrict__ A0, const float* __restrict__ A1,
    const float* __restrict__ A2,
    const float* __restrict__ W0, const float* __restrict__ W1,
    const float* __restrict__ W2,
    float* __restrict__ C0, float* __restrict__ C1, float* __restrict__ C2,
    const int* __restrict__ Mask)
{
    __shared__ u32 As[128 * LDA];
    __shared__ u32 Bs[32 * LDB];

    if (blockIdx.z >= 3) {
        // mask pack: 1024 blocks x 8 warps = 8192 warps (full DRAM parallelism)
        const int lane = threadIdx.x & 31;
        const int pid  = (blockIdx.z - 3) * 256 + blockIdx.x + 4 * blockIdx.y;
        const int wid  = pid * 8 + (threadIdx.x >> 5);    // 0..8191
        const int nw   = 8192;
        for (int w0 = wid; w0 < MWORDS; w0 += 4 * nw) {
            int w1 = w0 + nw, w2 = w0 + 2 * nw, w3 = w0 + 3 * nw;
            int v0 = Mask[(size_t)w0 * 32 + lane];
            int v1 = (w1 < MWORDS) ? Mask[(size_t)w1 * 32 + lane] : 0;
            int v2 = (w2 < MWORDS) ? Mask[(size_t)w2 * 32 + lane] : 0;
            int v3 = (w3 < MWORDS) ? Mask[(size_t)w3 * 32 + lane] : 0;
            u32 b0 = __ballot_sync(0xffffffffu, v0 != 0);
            u32 b1 = __ballot_sync(0xffffffffu, v1 != 0);
            u32 b2 = __ballot_sync(0xffffffffu, v2 != 0);
            u32 b3 = __ballot_sync(0xffffffffu, v3 != 0);
            if (lane == 0) {
                Mpg[w0] = b0;
                if (w1 < MWORDS) Mpg[w1] = b1;
                if (w2 < MWORDS) Mpg[w2] = b2;
                if (w3 < MWORDS) Mpg[w3] = b3;
            }
        }
        return;
    }

    const float* A; const float* Bw; float* C;
    if (blockIdx.z == 0)      { A = A0; Bw = W0; C = C0; }
    else if (blockIdx.z == 1) { A = A1; Bw = W1; C = C1; }
    else                      { A = A2; Bw = W2; C = C2; }
    gemm_tf32_body<true>(A, Bw, C, As, Bs);
}

// ---------------------------------------------------------------------------
// Wo projection: tf32 GEMM, fp32 output.
// ---------------------------------------------------------------------------
__global__ __launch_bounds__(256) void gemm_wo_tf32(
    const float* __restrict__ A, const float* __restrict__ Bw,
    float* __restrict__ C)
{
    __shared__ u32 As[128 * LDA];
    __shared__ u32 Bs[32 * LDB];
    gemm_tf32_body<false>(A, Bw, C, As, Bs);
}

// ---------------------------------------------------------------------------
// Flash attention v11 (proven ~654us):
//  - tf32 mma, Bq=128, 256 threads = 8 warps, warp tile m16 x n64
//  - Q fragments in registers (no Q smem, no Q LDS in loop)
//  - permuted K (slot(k)=((k&3)<<1)|(k>>2) in 8-groups): S accumulator regs
//    ARE the PV A-fragments -> zero shuffles; V natural [k][d]
//  - mask from pre-packed bits (Mpg): 4 u32 loads per thread per iter
//  - cp.async double-buffered K/V
// smem: 2*K[64][68] + 2*V[64][72] = 71680 B -> 2 CTAs/SM, 16 warps/SM.
// ---------------------------------------------------------------------------
#define LDK 68
#define LDV 72
#define KBW  (64 * LDK)
#define VBW  (64 * LDV)
#define KOFF 0
#define VOFF (2 * KBW)
#define FSMEM ((2 * KBW + 2 * VBW) * 4)   // 71680

__global__ void __launch_bounds__(256, 2) flash_attn(
    const float* __restrict__ Q, const float* __restrict__ K,
    const float* __restrict__ V, float* __restrict__ O)
{
    extern __shared__ u32 dsm[];
    const u32 sbase = (u32)__cvta_generic_to_shared(dsm);

    const int tid  = threadIdx.x;
    const int lane = tid & 31;
    const int w    = tid >> 5;       // warp 0..7 -> q rows [16w, 16w+16)
    const int g    = lane >> 2;
    const int c    = lane & 3;
    const int q0 = blockIdx.x * 128;
    const int h  = blockIdx.y;
    const int b  = blockIdx.z;

    // K/V coop load: 64 rows, 4 threads per row (16 floats each)
    const int r2 = tid >> 2;
    const int qt = (tid & 3) * 16;
    const int prow = (r2 & 56) | (((r2 & 3) << 1) | ((r2 & 7) >> 2));

    const float* ksrc0 = K + ((size_t)(b * Ss + r2)) * HDv + h * 64 + qt;
    const float* vsrc0 = V + ((size_t)(b * Ss + r2)) * HDv + h * 64 + qt;
    const u32 kdst0 = sbase + (KOFF + prow * LDK + qt) * 4;
    const u32 vdst0 = sbase + (VOFF + r2 * LDV + qt) * 4;

    // prologue: issue K/V tile 0 into buffer 0
#pragma unroll
    for (int j = 0; j < 4; ++j) {
        cpa16(kdst0 + 16 * j, ksrc0 + 4 * j);
        cpa16(vdst0 + 16 * j, vsrc0 + 4 * j);
    }
    cpa_commit();

    // Q fragments -> registers (Q already tf32-valued from projection epilogue)
    u32 qf[8][4];
    {
        const u32* q0p = (const u32*)(Q + (size_t)(b * Ss + q0 + 16 * w + g) * HDv + h * 64);
        const u32* q1p = q0p + 8 * HDv;
#pragma unroll
        for (int ks = 0; ks < 8; ++ks) {
            qf[ks][0] = q0p[ks * 8 + c];
            qf[ks][1] = q1p[ks * 8 + c];
            qf[ks][2] = q0p[ks * 8 + c + 4];
            qf[ks][3] = q1p[ks * 8 + c + 4];
        }
    }

    float m_[2], l_[2];
    float o[8][4];
    m_[0] = m_[1] = -CUDART_INF_F;
    l_[0] = l_[1] = 0.f;
#pragma unroll
    for (int nt = 0; nt < 8; ++nt)
#pragma unroll
        for (int j = 0; j < 4; ++j) o[nt][j] = 0.f;

    // packed-mask word bases (Ss/32 = 128 words per q-row)
    const size_t mw0 = ((size_t)((b * Hh + h) * Ss + q0 + 16 * w + g)) * 128;
    const size_t mw1 = mw0 + (size_t)8 * 128;

    for (int it = 0; it < Ss / 64; ++it) {
        const int buf = it & 1;
        __syncthreads();   // prev compute on buf^1 done -> safe to overwrite

        // mask words for this tile
        u32 mwa0 = Mpg[mw0 + it * 2], mwa1 = Mpg[mw0 + it * 2 + 1];
        u32 mwb0 = Mpg[mw1 + it * 2], mwb1 = Mpg[mw1 + it * 2 + 1];

        // issue next K/V tile into the other buffer
        if (it + 1 < Ss / 64) {
            const float* kp = ksrc0 + (size_t)(it + 1) * 64 * HDv;
            const float* vp = vsrc0 + (size_t)(it + 1) * 64 * HDv;
            const u32 kd = kdst0 + (buf ^ 1) * KBW * 4;
            const u32 vd = vdst0 + (buf ^ 1) * VBW * 4;
#pragma unroll
            for (int j = 0; j < 4; ++j) {
                cpa16(kd + 16 * j, kp + 4 * j);
                cpa16(vd + 16 * j, vp + 4 * j);
            }
        }
        cpa_commit();
        cpa_wait1();       // current tile arrived
        __syncthreads();   // visible to all warps

        const u32* Kc = dsm + KOFF + buf * KBW;
        const u32* Vc = dsm + VOFF + buf * VBW;

        // ---- S = Q K^T (K columns in permuted slot order) ----
        float s[8][4];
#pragma unroll
        for (int nt = 0; nt < 8; ++nt)
#pragma unroll
            for (int j = 0; j < 4; ++j) s[nt][j] = 0.f;

#pragma unroll
        for (int ks = 0; ks < 8; ++ks) {
#pragma unroll
            for (int nt = 0; nt < 8; ++nt) {
                u32 b0 = Kc[(nt * 8 + g) * LDK + ks * 8 + c];
                u32 b1 = Kc[(nt * 8 + g) * LDK + ks * 8 + c + 4];
                mma_tf32(s[nt][0], s[nt][1], s[nt][2], s[nt][3],
                         qf[ks][0], qf[ks][1], qf[ks][2], qf[ks][3], b0, b1);
            }
        }

        // ---- online softmax; P (tf32-rounded) stays in s[] ----
#pragma unroll
        for (int sb = 0; sb < 2; ++sb) {
            const int j0 = 2 * sb, j1 = 2 * sb + 1;
            const u32 wa = sb ? mwb0 : mwa0;   // cols [it*64, +32)
            const u32 wb = sb ? mwb1 : mwa1;   // cols [it*64+32, +32)
            float mt_ = -CUDART_INF_F;
#pragma unroll
            for (int nt = 0; nt < 8; ++nt) {
                const u32 word = (nt < 4) ? wa : wb;
                const int sh = ((nt & 3) * 8) + c;
                s[nt][j0] = ((word >> sh) & 1u)       ? -1e10f : s[nt][j0] * 0.125f;
                s[nt][j1] = ((word >> (sh + 4)) & 1u) ? -1e10f : s[nt][j1] * 0.125f;
                mt_ = fmaxf(mt_, fmaxf(s[nt][j0], s[nt][j1]));
            }
            mt_ = fmaxf(mt_, __shfl_xor_sync(0xffffffffu, mt_, 1));
            mt_ = fmaxf(mt_, __shfl_xor_sync(0xffffffffu, mt_, 2));
            float mnew = fmaxf(m_[sb], mt_);
            float corr = __expf(m_[sb] - mnew);
            m_[sb] = mnew;
            float rs = 0.f;
#pragma unroll
            for (int nt = 0; nt < 8; ++nt) {
                float p0 = __uint_as_float(to_tf32(__expf(s[nt][j0] - mnew)));
                float p1 = __uint_as_float(to_tf32(__expf(s[nt][j1] - mnew)));
                rs += p0 + p1;
                s[nt][j0] = p0;
                s[nt][j1] = p1;
                o[nt][j0] *= corr;
                o[nt][j1] *= corr;
            }
            rs += __shfl_xor_sync(0xffffffffu, rs, 1);
            rs += __shfl_xor_sync(0xffffffffu, rs, 2);
            l_[sb] = l_[sb] * corr + rs;
        }

        // ---- O += P V : A-fragments straight from s[] ----
#pragma unroll
        for (int kc = 0; kc < 8; ++kc) {
#pragma unroll
            for (int nt = 0; nt < 8; ++nt) {
                u32 b0 = Vc[(kc * 8 + c)     * LDV + nt * 8 + g];
                u32 b1 = Vc[(kc * 8 + c + 4) * LDV + nt * 8 + g];
                mma_tf32(o[nt][0], o[nt][1], o[nt][2], o[nt][3],
                         __float_as_uint(s[kc][0]), __float_as_uint(s[kc][2]),
                         __float_as_uint(s[kc][1]), __float_as_uint(s[kc][3]),
                         b0, b1);
            }
        }
    }

    // normalize + write
    const float inv0 = 1.f / l_[0];
    const float inv1 = 1.f / l_[1];
    float* op0 = O + (size_t)(b * Ss + q0 + 16 * w + g) * HDv + h * 64;
    float* op1 = op0 + (size_t)8 * HDv;
#pragma unroll
    for (int nt = 0; nt < 8; ++nt) {
        *(float2*)(op0 + nt * 8 + 2 * c) = make_float2(o[nt][0] * inv0, o[nt][1] * inv0);
        *(float2*)(op1 + nt * 8 + 2 * c) = make_float2(o[nt][2] * inv1, o[nt][3] * inv1);
    }
}

// ---------------------------------------------------------------------------
// Launch
// ---------------------------------------------------------------------------
extern "C" void kernel_launch(void* const* d_in, const int* in_sizes, int n_in,
                              void* d_out, int out_size)
{
    (void)in_sizes; (void)n_in; (void)out_size;
    const float* queries = (const float*)d_in[0];
    const float* keys    = (const float*)d_in[1];
    const float* values  = (const float*)d_in[2];
    const int*   mask    = (const int*)d_in[3];
    const float* Wq = (const float*)d_in[4];
    const float* Wk = (const float*)d_in[5];
    const float* Wv = (const float*)d_in[6];
    const float* Wo = (const float*)d_in[7];

    void *qp, *kp, *vp, *op;
    cudaGetSymbolAddress(&qp, Qg);
    cudaGetSymbolAddress(&kp, Kg);
    cudaGetSymbolAddress(&vp, Vg);
    cudaGetSymbolAddress(&op, Og);

    cudaFuncSetAttribute(flash_attn,
                         cudaFuncAttributeMaxDynamicSharedMemorySize, FSMEM);

    // fused QKV projections + mask pack (z=3..6 pack at full parallelism)
    gemm_qkv_pack<<<dim3(4, 64, 7), 256>>>(queries, keys, values, Wq, Wk, Wv,
                                           (float*)qp, (float*)kp, (float*)vp,
                                           mask);

    flash_attn<<<dim3(Ss / 128, Hh, Bb), 256, FSMEM>>>(
        (const float*)qp, (const float*)kp, (const float*)vp, (float*)op);

    gemm_wo_tf32<<<dim3(4, 64), 256>>>((const float*)op, Wo, (float*)d_out);
}

// round 13
// speedup vs baseline: 1.8712x; 1.8377x over previous
#include <cuda_runtime.h>
#include <math_constants.h>

// Problem constants
#define Bb 2
#define Ss 4096
#define Hh 8
#define HDv 512   // H*D (D=64)

typedef unsigned long long ull;
typedef unsigned int u32;

// Scratch (device globals; no allocation allowed)
__device__ float Qg[Bb * Ss * HDv];
__device__ float Kg[Bb * Ss * HDv];
__device__ float Vg[Bb * Ss * HDv];
__device__ float Og[Bb * Ss * HDv];

#define MWORDS (Bb * Hh * Ss * (Ss / 32))   // 8,388,608 u32 = 33.5 MB
__device__ u32 Mpg[MWORDS];

// ---- helpers --------------------------------------------------------------
__device__ __forceinline__ u32 to_tf32(float f) {
    u32 r; asm("cvt.rna.tf32.f32 %0, %1;" : "=r"(r) : "f"(f)); return r;
}
__device__ __forceinline__ void mma_tf32(
    float& d0, float& d1, float& d2, float& d3,
    u32 a0, u32 a1, u32 a2, u32 a3, u32 b0, u32 b1)
{
    asm("mma.sync.aligned.m16n8k8.row.col.f32.tf32.tf32.f32 "
        "{%0,%1,%2,%3}, {%4,%5,%6,%7}, {%8,%9}, {%0,%1,%2,%3};"
        : "+f"(d0), "+f"(d1), "+f"(d2), "+f"(d3)
        : "r"(a0), "r"(a1), "r"(a2), "r"(a3), "r"(b0), "r"(b1));
}
__device__ __forceinline__ void cpa16(u32 dst, const void* src) {
    asm volatile("cp.async.cg.shared.global [%0], [%1], 16;"
                 :: "r"(dst), "l"(src) : "memory");
}
__device__ __forceinline__ void cpa_commit() {
    asm volatile("cp.async.commit_group;" ::: "memory");
}
__device__ __forceinline__ void cpa_wait1() {
    asm volatile("cp.async.wait_group 1;" ::: "memory");
}

// ---------------------------------------------------------------------------
// Mask bit-pack (STANDALONE — lean build, high occupancy; proven in round 10).
// int32 mask (268M elems, 1.07 GB) -> 1 bit/elem (33.5 MB).
// ---------------------------------------------------------------------------
__global__ __launch_bounds__(256) void pack_mask(const int* __restrict__ Mask)
{
    const int lane = threadIdx.x & 31;
    const int wid  = (blockIdx.x * blockDim.x + threadIdx.x) >> 5;
    const int nw   = (gridDim.x * blockDim.x) >> 5;

    for (int w0 = wid; w0 < MWORDS; w0 += 4 * nw) {
        int w1 = w0 + nw, w2 = w0 + 2 * nw, w3 = w0 + 3 * nw;
        int v0 = Mask[(size_t)w0 * 32 + lane];
        int v1 = (w1 < MWORDS) ? Mask[(size_t)w1 * 32 + lane] : 0;
        int v2 = (w2 < MWORDS) ? Mask[(size_t)w2 * 32 + lane] : 0;
        int v3 = (w3 < MWORDS) ? Mask[(size_t)w3 * 32 + lane] : 0;
        u32 b0 = __ballot_sync(0xffffffffu, v0 != 0);
        u32 b1 = __ballot_sync(0xffffffffu, v1 != 0);
        u32 b2 = __ballot_sync(0xffffffffu, v2 != 0);
        u32 b3 = __ballot_sync(0xffffffffu, v3 != 0);
        if (lane == 0) {
            Mpg[w0] = b0;
            if (w1 < MWORDS) Mpg[w1] = b1;
            if (w2 < MWORDS) Mpg[w2] = b2;
            if (w3 < MWORDS) Mpg[w3] = b3;
        }
    }
}

// ---------------------------------------------------------------------------
// GEMM core (tf32, CTA 128x128, BK=32, 256 threads, warp m32 x n64).
// ---------------------------------------------------------------------------
#define LDA 36
#define LDB 136

template <bool ROUND_OUT>
__device__ __forceinline__ void gemm_tf32_body(
    const float* __restrict__ A, const float* __restrict__ Bw,
    float* __restrict__ C, u32* As, u32* Bs)
{
    const int tid  = threadIdx.x;
    const int lane = tid & 31;
    const int w    = tid >> 5;
    const int g    = lane >> 2;
    const int c    = lane & 3;
    const int wm   = w & 3;
    const int wn   = w >> 2;
    const int bn = blockIdx.x * 128;
    const int bm = blockIdx.y * 128;

    const int arow = tid >> 1;
    const int akg  = (tid & 1) * 16;
    const int brow = tid >> 3;
    const int bcg  = (tid & 7) * 16;

    float acc[2][8][4];
#pragma unroll
    for (int mt = 0; mt < 2; ++mt)
#pragma unroll
        for (int nt = 0; nt < 8; ++nt)
#pragma unroll
            for (int j = 0; j < 4; ++j) acc[mt][nt][j] = 0.f;

    for (int k0 = 0; k0 < 512; k0 += 32) {
        {
            const float* Ap = A + (size_t)(bm + arow) * 512 + k0 + akg;
#pragma unroll
            for (int i = 0; i < 4; ++i) {
                float4 v = *(const float4*)(Ap + 4 * i);
                *(uint4*)&As[arow * LDA + akg + 4 * i] =
                    make_uint4(to_tf32(v.x), to_tf32(v.y), to_tf32(v.z), to_tf32(v.w));
            }
        }
        {
            const float* Bp = Bw + (size_t)(k0 + brow) * 512 + bn + bcg;
#pragma unroll
            for (int i = 0; i < 4; ++i) {
                float4 v = *(const float4*)(Bp + 4 * i);
                *(uint4*)&Bs[brow * LDB + bcg + 4 * i] =
                    make_uint4(to_tf32(v.x), to_tf32(v.y), to_tf32(v.z), to_tf32(v.w));
            }
        }
        __syncthreads();

#pragma unroll
        for (int ks = 0; ks < 4; ++ks) {
            u32 a[2][4];
#pragma unroll
            for (int mt = 0; mt < 2; ++mt) {
                int base = (32 * wm + 16 * mt + g) * LDA + ks * 8 + c;
                a[mt][0] = As[base];
                a[mt][1] = As[base + 8 * LDA];
                a[mt][2] = As[base + 4];
                a[mt][3] = As[base + 8 * LDA + 4];
            }
#pragma unroll
            for (int nt = 0; nt < 8; ++nt) {
                u32 b0 = Bs[(ks * 8 + c)     * LDB + 64 * wn + nt * 8 + g];
                u32 b1 = Bs[(ks * 8 + c + 4) * LDB + 64 * wn + nt * 8 + g];
#pragma unroll
                for (int mt = 0; mt < 2; ++mt)
                    mma_tf32(acc[mt][nt][0], acc[mt][nt][1], acc[mt][nt][2], acc[mt][nt][3],
                             a[mt][0], a[mt][1], a[mt][2], a[mt][3], b0, b1);
            }
        }
        __syncthreads();
    }

#pragma unroll
    for (int mt = 0; mt < 2; ++mt) {
        float* Cp0 = C + (size_t)(bm + 32 * wm + 16 * mt + g) * 512 + bn + 64 * wn;
        float* Cp1 = Cp0 + (size_t)8 * 512;
#pragma unroll
        for (int nt = 0; nt < 8; ++nt) {
            if (ROUND_OUT) {
                *(uint2*)(Cp0 + nt * 8 + 2 * c) =
                    make_uint2(to_tf32(acc[mt][nt][0]), to_tf32(acc[mt][nt][1]));
                *(uint2*)(Cp1 + nt * 8 + 2 * c) =
                    make_uint2(to_tf32(acc[mt][nt][2]), to_tf32(acc[mt][nt][3]));
            } else {
                *(float2*)(Cp0 + nt * 8 + 2 * c) =
                    make_float2(acc[mt][nt][0], acc[mt][nt][1]);
                *(float2*)(Cp1 + nt * 8 + 2 * c) =
                    make_float2(acc[mt][nt][2], acc[mt][nt][3]);
            }
        }
    }
}

// ---------------------------------------------------------------------------
// QKV projections (grid.z = 3): tf32 GEMM, tf32-rounded outputs.
// ---------------------------------------------------------------------------
__global__ __launch_bounds__(256) void gemm_qkv_tf32(
    const float* __restrict__ A0, const float* __restrict__ A1,
    const float* __restrict__ A2,
    const float* __restrict__ W0, const float* __restrict__ W1,
    const float* __restrict__ W2,
    float* __restrict__ C0, float* __restrict__ C1, float* __restrict__ C2)
{
    __shared__ u32 As[128 * LDA];
    __shared__ u32 Bs[32 * LDB];

    const float* A; const float* Bw; float* C;
    if (blockIdx.z == 0)      { A = A0; Bw = W0; C = C0; }
    else if (blockIdx.z == 1) { A = A1; Bw = W1; C = C1; }
    else                      { A = A2; Bw = W2; C = C2; }
    gemm_tf32_body<true>(A, Bw, C, As, Bs);
}

// ---------------------------------------------------------------------------
// Wo projection: tf32 GEMM, fp32 output (verified rel_err 7.24e-4).
// ---------------------------------------------------------------------------
__global__ __launch_bounds__(256) void gemm_wo_tf32(
    const float* __restrict__ A, const float* __restrict__ Bw,
    float* __restrict__ C)
{
    __shared__ u32 As[128 * LDA];
    __shared__ u32 Bs[32 * LDB];
    gemm_tf32_body<false>(A, Bw, C, As, Bs);
}

// ---------------------------------------------------------------------------
// Flash attention v11 (measured 654us in round 11):
//  - tf32 mma, Bq=128, 256 threads = 8 warps, warp tile m16 x n64
//  - Q fragments in registers (no Q smem, no Q LDS in loop)
//  - permuted K (slot(k)=((k&3)<<1)|(k>>2) in 8-groups): S accumulator regs
//    ARE the PV A-fragments -> zero shuffles; V natural [k][d]
//  - mask from pre-packed bits (Mpg): 4 u32 loads per thread per iter
//  - cp.async double-buffered K/V
// smem: 2*K[64][68] + 2*V[64][72] = 71680 B -> 2 CTAs/SM, 16 warps/SM.
// ---------------------------------------------------------------------------
#define LDK 68
#define LDV 72
#define KBW  (64 * LDK)
#define VBW  (64 * LDV)
#define KOFF 0
#define VOFF (2 * KBW)
#define FSMEM ((2 * KBW + 2 * VBW) * 4)   // 71680

__global__ void __launch_bounds__(256, 2) flash_attn(
    const float* __restrict__ Q, const float* __restrict__ K,
    const float* __restrict__ V, float* __restrict__ O)
{
    extern __shared__ u32 dsm[];
    const u32 sbase = (u32)__cvta_generic_to_shared(dsm);

    const int tid  = threadIdx.x;
    const int lane = tid & 31;
    const int w    = tid >> 5;       // warp 0..7 -> q rows [16w, 16w+16)
    const int g    = lane >> 2;
    const int c    = lane & 3;
    const int q0 = blockIdx.x * 128;
    const int h  = blockIdx.y;
    const int b  = blockIdx.z;

    // K/V coop load: 64 rows, 4 threads per row (16 floats each)
    const int r2 = tid >> 2;
    const int qt = (tid & 3) * 16;
    const int prow = (r2 & 56) | (((r2 & 3) << 1) | ((r2 & 7) >> 2));

    const float* ksrc0 = K + ((size_t)(b * Ss + r2)) * HDv + h * 64 + qt;
    const float* vsrc0 = V + ((size_t)(b * Ss + r2)) * HDv + h * 64 + qt;
    const u32 kdst0 = sbase + (KOFF + prow * LDK + qt) * 4;
    const u32 vdst0 = sbase + (VOFF + r2 * LDV + qt) * 4;

    // prologue: issue K/V tile 0 into buffer 0
#pragma unroll
    for (int j = 0; j < 4; ++j) {
        cpa16(kdst0 + 16 * j, ksrc0 + 4 * j);
        cpa16(vdst0 + 16 * j, vsrc0 + 4 * j);
    }
    cpa_commit();

    // Q fragments -> registers (Q already tf32-valued from projection epilogue)
    u32 qf[8][4];
    {
        const u32* q0p = (const u32*)(Q + (size_t)(b * Ss + q0 + 16 * w + g) * HDv + h * 64);
        const u32* q1p = q0p + 8 * HDv;
#pragma unroll
        for (int ks = 0; ks < 8; ++ks) {
            qf[ks][0] = q0p[ks * 8 + c];
            qf[ks][1] = q1p[ks * 8 + c];
            qf[ks][2] = q0p[ks * 8 + c + 4];
            qf[ks][3] = q1p[ks * 8 + c + 4];
        }
    }

    float m_[2], l_[2];
    float o[8][4];
    m_[0] = m_[1] = -CUDART_INF_F;
    l_[0] = l_[1] = 0.f;
#pragma unroll
    for (int nt = 0; nt < 8; ++nt)
#pragma unroll
        for (int j = 0; j < 4; ++j) o[nt][j] = 0.f;

    // packed-mask word bases (Ss/32 = 128 words per q-row)
    const size_t mw0 = ((size_t)((b * Hh + h) * Ss + q0 + 16 * w + g)) * 128;
    const size_t mw1 = mw0 + (size_t)8 * 128;

    for (int it = 0; it < Ss / 64; ++it) {
        const int buf = it & 1;
        __syncthreads();   // prev compute on buf^1 done -> safe to overwrite

        // mask words for this tile
        u32 mwa0 = Mpg[mw0 + it * 2], mwa1 = Mpg[mw0 + it * 2 + 1];
        u32 mwb0 = Mpg[mw1 + it * 2], mwb1 = Mpg[mw1 + it * 2 + 1];

        // issue next K/V tile into the other buffer
        if (it + 1 < Ss / 64) {
            const float* kp = ksrc0 + (size_t)(it + 1) * 64 * HDv;
            const float* vp = vsrc0 + (size_t)(it + 1) * 64 * HDv;
            const u32 kd = kdst0 + (buf ^ 1) * KBW * 4;
            const u32 vd = vdst0 + (buf ^ 1) * VBW * 4;
#pragma unroll
            for (int j = 0; j < 4; ++j) {
                cpa16(kd + 16 * j, kp + 4 * j);
                cpa16(vd + 16 * j, vp + 4 * j);
            }
        }
        cpa_commit();
        cpa_wait1();       // current tile arrived
        __syncthreads();   // visible to all warps

        const u32* Kc = dsm + KOFF + buf * KBW;
        const u32* Vc = dsm + VOFF + buf * VBW;

        // ---- S = Q K^T (K columns in permuted slot order) ----
        float s[8][4];
#pragma unroll
        for (int nt = 0; nt < 8; ++nt)
#pragma unroll
            for (int j = 0; j < 4; ++j) s[nt][j] = 0.f;

#pragma unroll
        for (int ks = 0; ks < 8; ++ks) {
#pragma unroll
            for (int nt = 0; nt < 8; ++nt) {
                u32 b0 = Kc[(nt * 8 + g) * LDK + ks * 8 + c];
                u32 b1 = Kc[(nt * 8 + g) * LDK + ks * 8 + c + 4];
                mma_tf32(s[nt][0], s[nt][1], s[nt][2], s[nt][3],
                         qf[ks][0], qf[ks][1], qf[ks][2], qf[ks][3], b0, b1);
            }
        }

        // ---- online softmax; P (tf32-rounded) stays in s[] ----
#pragma unroll
        for (int sb = 0; sb < 2; ++sb) {
            const int j0 = 2 * sb, j1 = 2 * sb + 1;
            const u32 wa = sb ? mwb0 : mwa0;   // cols [it*64, +32)
            const u32 wb = sb ? mwb1 : mwa1;   // cols [it*64+32, +32)
            float mt_ = -CUDART_INF_F;
#pragma unroll
            for (int nt = 0; nt < 8; ++nt) {
                const u32 word = (nt < 4) ? wa : wb;
                const int sh = ((nt & 3) * 8) + c;
                s[nt][j0] = ((word >> sh) & 1u)       ? -1e10f : s[nt][j0] * 0.125f;
                s[nt][j1] = ((word >> (sh + 4)) & 1u) ? -1e10f : s[nt][j1] * 0.125f;
                mt_ = fmaxf(mt_, fmaxf(s[nt][j0], s[nt][j1]));
            }
            mt_ = fmaxf(mt_, __shfl_xor_sync(0xffffffffu, mt_, 1));
            mt_ = fmaxf(mt_, __shfl_xor_sync(0xffffffffu, mt_, 2));
            float mnew = fmaxf(m_[sb], mt_);
            float corr = __expf(m_[sb] - mnew);
            m_[sb] = mnew;
            float rs = 0.f;
#pragma unroll
            for (int nt = 0; nt < 8; ++nt) {
                float p0 = __uint_as_float(to_tf32(__expf(s[nt][j0] - mnew)));
                float p1 = __uint_as_float(to_tf32(__expf(s[nt][j1] - mnew)));
                rs += p0 + p1;
                s[nt][j0] = p0;
                s[nt][j1] = p1;
                o[nt][j0] *= corr;
                o[nt][j1] *= corr;
            }
            rs += __shfl_xor_sync(0xffffffffu, rs, 1);
            rs += __shfl_xor_sync(0xffffffffu, rs, 2);
            l_[sb] = l_[sb] * corr + rs;
        }

        // ---- O += P V : A-fragments straight from s[] ----
#pragma unroll
        for (int kc = 0; kc < 8; ++kc) {
#pragma unroll
            for (int nt = 0; nt < 8; ++nt) {
                u32 b0 = Vc[(kc * 8 + c)     * LDV + nt * 8 + g];
                u32 b1 = Vc[(kc * 8 + c + 4) * LDV + nt * 8 + g];
                mma_tf32(o[nt][0], o[nt][1], o[nt][2], o[nt][3],
                         __float_as_uint(s[kc][0]), __float_as_uint(s[kc][2]),
                         __float_as_uint(s[kc][1]), __float_as_uint(s[kc][3]),
                         b0, b1);
            }
        }
    }

    // normalize + write
    const float inv0 = 1.f / l_[0];
    const float inv1 = 1.f / l_[1];
    float* op0 = O + (size_t)(b * Ss + q0 + 16 * w + g) * HDv + h * 64;
    float* op1 = op0 + (size_t)8 * HDv;
#pragma unroll
    for (int nt = 0; nt < 8; ++nt) {
        *(float2*)(op0 + nt * 8 + 2 * c) = make_float2(o[nt][0] * inv0, o[nt][1] * inv0);
        *(float2*)(op1 + nt * 8 + 2 * c) = make_float2(o[nt][2] * inv1, o[nt][3] * inv1);
    }
}

// ---------------------------------------------------------------------------
// Launch: 4 separate kernels, each with its own optimal resource footprint.
// ---------------------------------------------------------------------------
extern "C" void kernel_launch(void* const* d_in, const int* in_sizes, int n_in,
                              void* d_out, int out_size)
{
    (void)in_sizes; (void)n_in; (void)out_size;
    const float* queries = (const float*)d_in[0];
    const float* keys    = (const float*)d_in[1];
    const float* values  = (const float*)d_in[2];
    const int*   mask    = (const int*)d_in[3];
    const float* Wq = (const float*)d_in[4];
    const float* Wk = (const float*)d_in[5];
    const float* Wv = (const float*)d_in[6];
    const float* Wo = (const float*)d_in[7];

    void *qp, *kp, *vp, *op;
    cudaGetSymbolAddress(&qp, Qg);
    cudaGetSymbolAddress(&kp, Kg);
    cudaGetSymbolAddress(&vp, Vg);
    cudaGetSymbolAddress(&op, Og);

    cudaFuncSetAttribute(flash_attn,
                         cudaFuncAttributeMaxDynamicSharedMemorySize, FSMEM);

    pack_mask<<<1024, 256>>>(mask);

    gemm_qkv_tf32<<<dim3(4, 64, 3), 256>>>(queries, keys, values, Wq, Wk, Wv,
                                           (float*)qp, (float*)kp, (float*)vp);

    flash_attn<<<dim3(Ss / 128, Hh, Bb), 256, FSMEM>>>(
        (const float*)qp, (const float*)kp, (const float*)vp, (float*)op);

    gemm_wo_tf32<<<dim3(4, 64), 256>>>((const float*)op, Wo, (float*)d_out);
}

// round 15
// speedup vs baseline: 1.9113x; 1.0214x over previous
#include <cuda_runtime.h>
#include <math_constants.h>

// Problem constants
#define Bb 2
#define Ss 4096
#define Hh 8
#define HDv 512   // H*D (D=64)

typedef unsigned long long ull;
typedef unsigned int u32;

// Scratch (device globals; no allocation allowed)
__device__ float Qg[Bb * Ss * HDv];
__device__ float Kg[Bb * Ss * HDv];
__device__ float Vg[Bb * Ss * HDv];
__device__ float Og[Bb * Ss * HDv];

#define MWORDS (Bb * Hh * Ss * (Ss / 32))   // 8,388,608 u32 = 33.5 MB
__device__ u32 Mpg[MWORDS];

// ---- helpers --------------------------------------------------------------
__device__ __forceinline__ u32 to_tf32(float f) {
    u32 r; asm("cvt.rna.tf32.f32 %0, %1;" : "=r"(r) : "f"(f)); return r;
}
__device__ __forceinline__ uint4 cvt4(float4 v) {
    return make_uint4(to_tf32(v.x), to_tf32(v.y), to_tf32(v.z), to_tf32(v.w));
}
__device__ __forceinline__ void mma_tf32(
    float& d0, float& d1, float& d2, float& d3,
    u32 a0, u32 a1, u32 a2, u32 a3, u32 b0, u32 b1)
{
    asm("mma.sync.aligned.m16n8k8.row.col.f32.tf32.tf32.f32 "
        "{%0,%1,%2,%3}, {%4,%5,%6,%7}, {%8,%9}, {%0,%1,%2,%3};"
        : "+f"(d0), "+f"(d1), "+f"(d2), "+f"(d3)
        : "r"(a0), "r"(a1), "r"(a2), "r"(a3), "r"(b0), "r"(b1));
}
__device__ __forceinline__ void cpa16(u32 dst, const void* src) {
    asm volatile("cp.async.cg.shared.global [%0], [%1], 16;"
                 :: "r"(dst), "l"(src) : "memory");
}
__device__ __forceinline__ void cpa_commit() {
    asm volatile("cp.async.commit_group;" ::: "memory");
}
__device__ __forceinline__ void cpa_wait0() {
    asm volatile("cp.async.wait_group 0;" ::: "memory");
}

// ---------------------------------------------------------------------------
// Mask bit-pack (standalone, lean; proven ~200us).
// ---------------------------------------------------------------------------
__global__ __launch_bounds__(256) void pack_mask(const int* __restrict__ Mask)
{
    const int lane = threadIdx.x & 31;
    const int wid  = (blockIdx.x * blockDim.x + threadIdx.x) >> 5;
    const int nw   = (gridDim.x * blockDim.x) >> 5;

    for (int w0 = wid; w0 < MWORDS; w0 += 4 * nw) {
        int w1 = w0 + nw, w2 = w0 + 2 * nw, w3 = w0 + 3 * nw;
        int v0 = Mask[(size_t)w0 * 32 + lane];
        int v1 = (w1 < MWORDS) ? Mask[(size_t)w1 * 32 + lane] : 0;
        int v2 = (w2 < MWORDS) ? Mask[(size_t)w2 * 32 + lane] : 0;
        int v3 = (w3 < MWORDS) ? Mask[(size_t)w3 * 32 + lane] : 0;
        u32 b0 = __ballot_sync(0xffffffffu, v0 != 0);
        u32 b1 = __ballot_sync(0xffffffffu, v1 != 0);
        u32 b2 = __ballot_sync(0xffffffffu, v2 != 0);
        u32 b3 = __ballot_sync(0xffffffffu, v3 != 0);
        if (lane == 0) {
            Mpg[w0] = b0;
            if (w1 < MWORDS) Mpg[w1] = b1;
            if (w2 < MWORDS) Mpg[w2] = b2;
            if (w3 < MWORDS) Mpg[w3] = b3;
        }
    }
}

// ---------------------------------------------------------------------------
// GEMM core (tf32, CTA 128x128, BK=32, 256 threads, warp m32 x n64) with
// REGISTER PREFETCH double buffering: LDG for tile k+1 issued right after the
// barrier, consumed next iteration -> global-load latency off critical path.
// cvt.rna retained (identical arithmetic to previous rounds).
// ---------------------------------------------------------------------------
#define LDA 36
#define LDB 136

template <bool ROUND_OUT>
__device__ __forceinline__ void gemm_tf32_body(
    const float* __restrict__ A, const float* __restrict__ Bw,
    float* __restrict__ C, u32* As, u32* Bs)
{
    const int tid  = threadIdx.x;
    const int lane = tid & 31;
    const int w    = tid >> 5;
    const int g    = lane >> 2;
    const int c    = lane & 3;
    const int wm   = w & 3;
    const int wn   = w >> 2;
    const int bn = blockIdx.x * 128;
    const int bm = blockIdx.y * 128;

    const int arow = tid >> 1;
    const int akg  = (tid & 1) * 16;
    const int brow = tid >> 3;
    const int bcg  = (tid & 7) * 16;

    const float* Abase = A + (size_t)(bm + arow) * 512 + akg;
    const float* Bbase = Bw + (size_t)brow * 512 + bn + bcg;

    float acc[2][8][4];
#pragma unroll
    for (int mt = 0; mt < 2; ++mt)
#pragma unroll
        for (int nt = 0; nt < 8; ++nt)
#pragma unroll
            for (int j = 0; j < 4; ++j) acc[mt][nt][j] = 0.f;

    // preload tile 0 into registers
    float4 pa[4], pb[4];
#pragma unroll
    for (int i = 0; i < 4; ++i) {
        pa[i] = *(const float4*)(Abase + 4 * i);
        pb[i] = *(const float4*)(Bbase + 4 * i);
    }

    for (int k0 = 0; k0 < 512; k0 += 32) {
        // store prefetched tile (rna-converted) to smem
#pragma unroll
        for (int i = 0; i < 4; ++i) {
            *(uint4*)&As[arow * LDA + akg + 4 * i] = cvt4(pa[i]);
            *(uint4*)&Bs[brow * LDB + bcg + 4 * i] = cvt4(pb[i]);
        }
        __syncthreads();

        // prefetch next tile (latency hidden behind the MMA block below)
        if (k0 + 32 < 512) {
            const float* Ap = Abase + (k0 + 32);
            const float* Bp = Bbase + (size_t)(k0 + 32) * 512;
#pragma unroll
            for (int i = 0; i < 4; ++i) {
                pa[i] = *(const float4*)(Ap + 4 * i);
                pb[i] = *(const float4*)(Bp + 4 * i);
            }
        }

#pragma unroll
        for (int ks = 0; ks < 4; ++ks) {
            u32 a[2][4];
#pragma unroll
            for (int mt = 0; mt < 2; ++mt) {
                int base = (32 * wm + 16 * mt + g) * LDA + ks * 8 + c;
                a[mt][0] = As[base];
                a[mt][1] = As[base + 8 * LDA];
                a[mt][2] = As[base + 4];
                a[mt][3] = As[base + 8 * LDA + 4];
            }
#pragma unroll
            for (int nt = 0; nt < 8; ++nt) {
                u32 b0 = Bs[(ks * 8 + c)     * LDB + 64 * wn + nt * 8 + g];
                u32 b1 = Bs[(ks * 8 + c + 4) * LDB + 64 * wn + nt * 8 + g];
#pragma unroll
                for (int mt = 0; mt < 2; ++mt)
                    mma_tf32(acc[mt][nt][0], acc[mt][nt][1], acc[mt][nt][2], acc[mt][nt][3],
                             a[mt][0], a[mt][1], a[mt][2], a[mt][3], b0, b1);
            }
        }
        __syncthreads();
    }

#pragma unroll
    for (int mt = 0; mt < 2; ++mt) {
        float* Cp0 = C + (size_t)(bm + 32 * wm + 16 * mt + g) * 512 + bn + 64 * wn;
        float* Cp1 = Cp0 + (size_t)8 * 512;
#pragma unroll
        for (int nt = 0; nt < 8; ++nt) {
            if (ROUND_OUT) {
                *(uint2*)(Cp0 + nt * 8 + 2 * c) =
                    make_uint2(to_tf32(acc[mt][nt][0]), to_tf32(acc[mt][nt][1]));
                *(uint2*)(Cp1 + nt * 8 + 2 * c) =
                    make_uint2(to_tf32(acc[mt][nt][2]), to_tf32(acc[mt][nt][3]));
            } else {
                *(float2*)(Cp0 + nt * 8 + 2 * c) =
                    make_float2(acc[mt][nt][0], acc[mt][nt][1]);
                *(float2*)(Cp1 + nt * 8 + 2 * c) =
                    make_float2(acc[mt][nt][2], acc[mt][nt][3]);
            }
        }
    }
}

// ---------------------------------------------------------------------------
// QKV projections (grid.z = 3): tf32 GEMM, tf32-rounded outputs.
// ---------------------------------------------------------------------------
__global__ __launch_bounds__(256) void gemm_qkv_tf32(
    const float* __restrict__ A0, const float* __restrict__ A1,
    const float* __restrict__ A2,
    const float* __restrict__ W0, const float* __restrict__ W1,
    const float* __restrict__ W2,
    float* __restrict__ C0, float* __restrict__ C1, float* __restrict__ C2)
{
    __shared__ u32 As[128 * LDA];
    __shared__ u32 Bs[32 * LDB];

    const float* A; const float* Bw; float* C;
    if (blockIdx.z == 0)      { A = A0; Bw = W0; C = C0; }
    else if (blockIdx.z == 1) { A = A1; Bw = W1; C = C1; }
    else                      { A = A2; Bw = W2; C = C2; }
    gemm_tf32_body<true>(A, Bw, C, As, Bs);
}

// ---------------------------------------------------------------------------
// Wo projection: tf32 GEMM, fp32 output (verified rel_err 7.24e-4).
// ---------------------------------------------------------------------------
__global__ __launch_bounds__(256) void gemm_wo_tf32(
    const float* __restrict__ A, const float* __restrict__ Bw,
    float* __restrict__ C)
{
    __shared__ u32 As[128 * LDA];
    __shared__ u32 Bs[32 * LDB];
    gemm_tf32_body<false>(A, Bw, C, As, Bs);
}

// ---------------------------------------------------------------------------
// Flash attention v12: single barrier per k-tile.
// Loop order: wait_all -> sync (visibility + overwrite-protection, since
// compute(it-1) precedes it in program order) -> issue tile it+1 into buf^1
// -> compute tile it. Everything else identical to v11 (654us measured).
// smem: 2*K[64][68] + 2*V[64][72] = 71680 B -> 2 CTAs/SM, 16 warps/SM.
// ---------------------------------------------------------------------------
#define LDK 68
#define LDV 72
#define KBW  (64 * LDK)
#define VBW  (64 * LDV)
#define KOFF 0
#define VOFF (2 * KBW)
#define FSMEM ((2 * KBW + 2 * VBW) * 4)   // 71680

__global__ void __launch_bounds__(256, 2) flash_attn(
    const float* __restrict__ Q, const float* __restrict__ K,
    const float* __restrict__ V, float* __restrict__ O)
{
    extern __shared__ u32 dsm[];
    const u32 sbase = (u32)__cvta_generic_to_shared(dsm);

    const int tid  = threadIdx.x;
    const int lane = tid & 31;
    const int w    = tid >> 5;       // warp 0..7 -> q rows [16w, 16w+16)
    const int g    = lane >> 2;
    const int c    = lane & 3;
    const int q0 = blockIdx.x * 128;
    const int h  = blockIdx.y;
    const int b  = blockIdx.z;

    // K/V coop load: 64 rows, 4 threads per row (16 floats each)
    const int r2 = tid >> 2;
    const int qt = (tid & 3) * 16;
    const int prow = (r2 & 56) | (((r2 & 3) << 1) | ((r2 & 7) >> 2));

    const float* ksrc0 = K + ((size_t)(b * Ss + r2)) * HDv + h * 64 + qt;
    const float* vsrc0 = V + ((size_t)(b * Ss + r2)) * HDv + h * 64 + qt;
    const u32 kdst0 = sbase + (KOFF + prow * LDK + qt) * 4;
    const u32 vdst0 = sbase + (VOFF + r2 * LDV + qt) * 4;

    // prologue: issue K/V tile 0 into buffer 0
#pragma unroll
    for (int j = 0; j < 4; ++j) {
        cpa16(kdst0 + 16 * j, ksrc0 + 4 * j);
        cpa16(vdst0 + 16 * j, vsrc0 + 4 * j);
    }
    cpa_commit();

    // Q fragments -> registers (Q already tf32-valued from projection epilogue)
    u32 qf[8][4];
    {
        const u32* q0p = (const u32*)(Q + (size_t)(b * Ss + q0 + 16 * w + g) * HDv + h * 64);
        const u32* q1p = q0p + 8 * HDv;
#pragma unroll
        for (int ks = 0; ks < 8; ++ks) {
            qf[ks][0] = q0p[ks * 8 + c];
            qf[ks][1] = q1p[ks * 8 + c];
            qf[ks][2] = q0p[ks * 8 + c + 4];
            qf[ks][3] = q1p[ks * 8 + c + 4];
        }
    }

    float m_[2], l_[2];
    float o[8][4];
    m_[0] = m_[1] = -CUDART_INF_F;
    l_[0] = l_[1] = 0.f;
#pragma unroll
    for (int nt = 0; nt < 8; ++nt)
#pragma unroll
        for (int j = 0; j < 4; ++j) o[nt][j] = 0.f;

    // packed-mask word bases (Ss/32 = 128 words per q-row)
    const size_t mw0 = ((size_t)((b * Hh + h) * Ss + q0 + 16 * w + g)) * 128;
    const size_t mw1 = mw0 + (size_t)8 * 128;

    for (int it = 0; it < Ss / 64; ++it) {
        const int buf = it & 1;

        // mask words for this tile (independent loads, issued before the wait)
        u32 mwa0 = Mpg[mw0 + it * 2], mwa1 = Mpg[mw0 + it * 2 + 1];
        u32 mwb0 = Mpg[mw1 + it * 2], mwb1 = Mpg[mw1 + it * 2 + 1];

        cpa_wait0();       // tile it landed (issued one compute-phase ago)
        __syncthreads();   // visibility; also: all warps done computing it-1

        // issue tile it+1 into the other buffer (safe: barrier above)
        if (it + 1 < Ss / 64) {
            const float* kp = ksrc0 + (size_t)(it + 1) * 64 * HDv;
            const float* vp = vsrc0 + (size_t)(it + 1) * 64 * HDv;
            const u32 kd = kdst0 + (buf ^ 1) * KBW * 4;
            const u32 vd = vdst0 + (buf ^ 1) * VBW * 4;
#pragma unroll
            for (int j = 0; j < 4; ++j) {
                cpa16(kd + 16 * j, kp + 4 * j);
                cpa16(vd + 16 * j, vp + 4 * j);
            }
            cpa_commit();
        }

        const u32* Kc = dsm + KOFF + buf * KBW;
        const u32* Vc = dsm + VOFF + buf * VBW;

        // ---- S = Q K^T (K columns in permuted slot order) ----
        float s[8][4];
#pragma unroll
        for (int nt = 0; nt < 8; ++nt)
#pragma unroll
            for (int j = 0; j < 4; ++j) s[nt][j] = 0.f;

#pragma unroll
        for (int ks = 0; ks < 8; ++ks) {
#pragma unroll
            for (int nt = 0; nt < 8; ++nt) {
                u32 b0 = Kc[(nt * 8 + g) * LDK + ks * 8 + c];
                u32 b1 = Kc[(nt * 8 + g) * LDK + ks * 8 + c + 4];
                mma_tf32(s[nt][0], s[nt][1], s[nt][2], s[nt][3],
                         qf[ks][0], qf[ks][1], qf[ks][2], qf[ks][3], b0, b1);
            }
        }

        // ---- online softmax; P (tf32-rounded) stays in s[] ----
#pragma unroll
        for (int sb = 0; sb < 2; ++sb) {
            const int j0 = 2 * sb, j1 = 2 * sb + 1;
            const u32 wa = sb ? mwb0 : mwa0;   // cols [it*64, +32)
            const u32 wb = sb ? mwb1 : mwa1;   // cols [it*64+32, +32)
            float mt_ = -CUDART_INF_F;
#pragma unroll
            for (int nt = 0; nt < 8; ++nt) {
                const u32 word = (nt < 4) ? wa : wb;
                const int sh = ((nt & 3) * 8) + c;
                s[nt][j0] = ((word >> sh) & 1u)       ? -1e10f : s[nt][j0] * 0.125f;
                s[nt][j1] = ((word >> (sh + 4)) & 1u) ? -1e10f : s[nt][j1] * 0.125f;
                mt_ = fmaxf(mt_, fmaxf(s[nt][j0], s[nt][j1]));
            }
            mt_ = fmaxf(mt_, __shfl_xor_sync(0xffffffffu, mt_, 1));
            mt_ = fmaxf(mt_, __shfl_xor_sync(0xffffffffu, mt_, 2));
            float mnew = fmaxf(m_[sb], mt_);
            float corr = __expf(m_[sb] - mnew);
            m_[sb] = mnew;
            float rs = 0.f;
#pragma unroll
            for (int nt = 0; nt < 8; ++nt) {
                float p0 = __uint_as_float(to_tf32(__expf(s[nt][j0] - mnew)));
                float p1 = __uint_as_float(to_tf32(__expf(s[nt][j1] - mnew)));
                rs += p0 + p1;
                s[nt][j0] = p0;
                s[nt][j1] = p1;
                o[nt][j0] *= corr;
                o[nt][j1] *= corr;
            }
            rs += __shfl_xor_sync(0xffffffffu, rs, 1);
            rs += __shfl_xor_sync(0xffffffffu, rs, 2);
            l_[sb] = l_[sb] * corr + rs;
        }

        // ---- O += P V : A-fragments straight from s[] ----
#pragma unroll
        for (int kc = 0; kc < 8; ++kc) {
#pragma unroll
            for (int nt = 0; nt < 8; ++nt) {
                u32 b0 = Vc[(kc * 8 + c)     * LDV + nt * 8 + g];
                u32 b1 = Vc[(kc * 8 + c + 4) * LDV + nt * 8 + g];
                mma_tf32(o[nt][0], o[nt][1], o[nt][2], o[nt][3],
                         __float_as_uint(s[kc][0]), __float_as_uint(s[kc][2]),
                         __float_as_uint(s[kc][1]), __float_as_uint(s[kc][3]),
                         b0, b1);
            }
        }
    }

    // normalize + write
    const float inv0 = 1.f / l_[0];
    const float inv1 = 1.f / l_[1];
    float* op0 = O + (size_t)(b * Ss + q0 + 16 * w + g) * HDv + h * 64;
    float* op1 = op0 + (size_t)8 * HDv;
#pragma unroll
    for (int nt = 0; nt < 8; ++nt) {
        *(float2*)(op0 + nt * 8 + 2 * c) = make_float2(o[nt][0] * inv0, o[nt][1] * inv0);
        *(float2*)(op1 + nt * 8 + 2 * c) = make_float2(o[nt][2] * inv1, o[nt][3] * inv1);
    }
}

// ---------------------------------------------------------------------------
// Launch: 4 separate kernels, each with its own optimal resource footprint.
// ---------------------------------------------------------------------------
extern "C" void kernel_launch(void* const* d_in, const int* in_sizes, int n_in,
                              void* d_out, int out_size)
{
    (void)in_sizes; (void)n_in; (void)out_size;
    const float* queries = (const float*)d_in[0];
    const float* keys    = (const float*)d_in[1];
    const float* values  = (const float*)d_in[2];
    const int*   mask    = (const int*)d_in[3];
    const float* Wq = (const float*)d_in[4];
    const float* Wk = (const float*)d_in[5];
    const float* Wv = (const float*)d_in[6];
    const float* Wo = (const float*)d_in[7];

    void *qp, *kp, *vp, *op;
    cudaGetSymbolAddress(&qp, Qg);
    cudaGetSymbolAddress(&kp, Kg);
    cudaGetSymbolAddress(&vp, Vg);
    cudaGetSymbolAddress(&op, Og);

    cudaFuncSetAttribute(flash_attn,
                         cudaFuncAttributeMaxDynamicSharedMemorySize, FSMEM);

    pack_mask<<<1024, 256>>>(mask);

    gemm_qkv_tf32<<<dim3(4, 64, 3), 256>>>(queries, keys, values, Wq, Wk, Wv,
                                           (float*)qp, (float*)kp, (float*)vp);

    flash_attn<<<dim3(Ss / 128, Hh, Bb), 256, FSMEM>>>(
        (const float*)qp, (const float*)kp, (const float*)vp, (float*)op);

    gemm_wo_tf32<<<dim3(4, 64), 256>>>((const float*)op, Wo, (float*)d_out);
}

// round 16
// speedup vs baseline: 1.9998x; 1.0463x over previous
#include <cuda_runtime.h>
#include <math_constants.h>

// Problem constants
#define Bb 2
#define Ss 4096
#define Hh 8
#define HDv 512   // H*D (D=64)

typedef unsigned long long ull;
typedef unsigned int u32;

// Scratch (device globals; no allocation allowed)
__device__ float Qg[Bb * Ss * HDv];
__device__ float Kg[Bb * Ss * HDv];
__device__ float Vg[Bb * Ss * HDv];
__device__ float Og[Bb * Ss * HDv];

#define MWORDS (Bb * Hh * Ss * (Ss / 32))   // 8,388,608 u32 = 33.5 MB
#define MSEGS  (MWORDS / 4)                 // 2,097,152 segments of 128 ints
__device__ u32 Mpg[MWORDS];

// ---- helpers --------------------------------------------------------------
__device__ __forceinline__ u32 to_tf32(float f) {
    u32 r; asm("cvt.rna.tf32.f32 %0, %1;" : "=r"(r) : "f"(f)); return r;
}
__device__ __forceinline__ uint4 cvt4(float4 v) {
    return make_uint4(to_tf32(v.x), to_tf32(v.y), to_tf32(v.z), to_tf32(v.w));
}
__device__ __forceinline__ void mma_tf32(
    float& d0, float& d1, float& d2, float& d3,
    u32 a0, u32 a1, u32 a2, u32 a3, u32 b0, u32 b1)
{
    asm("mma.sync.aligned.m16n8k8.row.col.f32.tf32.tf32.f32 "
        "{%0,%1,%2,%3}, {%4,%5,%6,%7}, {%8,%9}, {%0,%1,%2,%3};"
        : "+f"(d0), "+f"(d1), "+f"(d2), "+f"(d3)
        : "r"(a0), "r"(a1), "r"(a2), "r"(a3), "r"(b0), "r"(b1));
}
__device__ __forceinline__ void cpa16(u32 dst, const void* src) {
    asm volatile("cp.async.cg.shared.global [%0], [%1], 16;"
                 :: "r"(dst), "l"(src) : "memory");
}
__device__ __forceinline__ void cpa_commit() {
    asm volatile("cp.async.commit_group;" ::: "memory");
}
__device__ __forceinline__ void cpa_wait0() {
    asm volatile("cp.async.wait_group 0;" ::: "memory");
}

// ---------------------------------------------------------------------------
// Mask bit-pack v2: int4 loads (16B/lane), 8-deep unroll for in-flight bytes.
// Each warp+segment covers 128 ints -> 4 output words.
//   lane i loads int4 at seg*128 + 4i; element 4i+k -> word (i>>3), bit 4(i&7)+k.
//   nibble per lane, OR-reduced over the 8-lane group via 3 shfl_xor.
// Bit layout identical to the ballot version (verified mapping above).
// ---------------------------------------------------------------------------
__global__ __launch_bounds__(256) void pack_mask(const int* __restrict__ Mask)
{
    const int lane = threadIdx.x & 31;
    const int sub  = lane >> 3;     // word index within segment (0..3)
    const int oct  = lane & 7;      // position within 8-lane group
    const int wid  = (blockIdx.x * blockDim.x + threadIdx.x) >> 5;
    const int nw   = (gridDim.x * blockDim.x) >> 5;   // 8192 warps

    const int4* M4 = (const int4*)Mask;

    for (int seg = wid; seg < MSEGS; seg += 8 * nw) {
        int4 v[8];
        int  sg[8];
#pragma unroll
        for (int u = 0; u < 8; ++u) {
            sg[u] = seg + u * nw;
            v[u] = (sg[u] < MSEGS) ? M4[(size_t)sg[u] * 32 + lane]
                                   : make_int4(0, 0, 0, 0);
        }
#pragma unroll
        for (int u = 0; u < 8; ++u) {
            u32 nib = (v[u].x != 0 ? 1u : 0u) | (v[u].y != 0 ? 2u : 0u)
                    | (v[u].z != 0 ? 4u : 0u) | (v[u].w != 0 ? 8u : 0u);
            u32 word = nib << (4 * oct);
            word |= __shfl_xor_sync(0xffffffffu, word, 1);
            word |= __shfl_xor_sync(0xffffffffu, word, 2);
            word |= __shfl_xor_sync(0xffffffffu, word, 4);
            if (oct == 0 && sg[u] < MSEGS)
                Mpg[(size_t)sg[u] * 4 + sub] = word;
        }
    }
}

// ---------------------------------------------------------------------------
// GEMM core (tf32, CTA 128x128, BK=32, 256 threads, warp m32 x n64) with
// register-prefetch double buffering. cvt.rna retained (identical arithmetic).
// ---------------------------------------------------------------------------
#define LDA 36
#define LDB 136

template <bool ROUND_OUT>
__device__ __forceinline__ void gemm_tf32_body(
    const float* __restrict__ A, const float* __restrict__ Bw,
    float* __restrict__ C, u32* As, u32* Bs)
{
    const int tid  = threadIdx.x;
    const int lane = tid & 31;
    const int w    = tid >> 5;
    const int g    = lane >> 2;
    const int c    = lane & 3;
    const int wm   = w & 3;
    const int wn   = w >> 2;
    const int bn = blockIdx.x * 128;
    const int bm = blockIdx.y * 128;

    const int arow = tid >> 1;
    const int akg  = (tid & 1) * 16;
    const int brow = tid >> 3;
    const int bcg  = (tid & 7) * 16;

    const float* Abase = A + (size_t)(bm + arow) * 512 + akg;
    const float* Bbase = Bw + (size_t)brow * 512 + bn + bcg;

    float acc[2][8][4];
#pragma unroll
    for (int mt = 0; mt < 2; ++mt)
#pragma unroll
        for (int nt = 0; nt < 8; ++nt)
#pragma unroll
            for (int j = 0; j < 4; ++j) acc[mt][nt][j] = 0.f;

    float4 pa[4], pb[4];
#pragma unroll
    for (int i = 0; i < 4; ++i) {
        pa[i] = *(const float4*)(Abase + 4 * i);
        pb[i] = *(const float4*)(Bbase + 4 * i);
    }

    for (int k0 = 0; k0 < 512; k0 += 32) {
#pragma unroll
        for (int i = 0; i < 4; ++i) {
            *(uint4*)&As[arow * LDA + akg + 4 * i] = cvt4(pa[i]);
            *(uint4*)&Bs[brow * LDB + bcg + 4 * i] = cvt4(pb[i]);
        }
        __syncthreads();

        if (k0 + 32 < 512) {
            const float* Ap = Abase + (k0 + 32);
            const float* Bp = Bbase + (size_t)(k0 + 32) * 512;
#pragma unroll
            for (int i = 0; i < 4; ++i) {
                pa[i] = *(const float4*)(Ap + 4 * i);
                pb[i] = *(const float4*)(Bp + 4 * i);
            }
        }

#pragma unroll
        for (int ks = 0; ks < 4; ++ks) {
            u32 a[2][4];
#pragma unroll
            for (int mt = 0; mt < 2; ++mt) {
                int base = (32 * wm + 16 * mt + g) * LDA + ks * 8 + c;
                a[mt][0] = As[base];
                a[mt][1] = As[base + 8 * LDA];
                a[mt][2] = As[base + 4];
                a[mt][3] = As[base + 8 * LDA + 4];
            }
#pragma unroll
            for (int nt = 0; nt < 8; ++nt) {
                u32 b0 = Bs[(ks * 8 + c)     * LDB + 64 * wn + nt * 8 + g];
                u32 b1 = Bs[(ks * 8 + c + 4) * LDB + 64 * wn + nt * 8 + g];
#pragma unroll
                for (int mt = 0; mt < 2; ++mt)
                    mma_tf32(acc[mt][nt][0], acc[mt][nt][1], acc[mt][nt][2], acc[mt][nt][3],
                             a[mt][0], a[mt][1], a[mt][2], a[mt][3], b0, b1);
            }
        }
        __syncthreads();
    }

#pragma unroll
    for (int mt = 0; mt < 2; ++mt) {
        float* Cp0 = C + (size_t)(bm + 32 * wm + 16 * mt + g) * 512 + bn + 64 * wn;
        float* Cp1 = Cp0 + (size_t)8 * 512;
#pragma unroll
        for (int nt = 0; nt < 8; ++nt) {
            if (ROUND_OUT) {
                *(uint2*)(Cp0 + nt * 8 + 2 * c) =
                    make_uint2(to_tf32(acc[mt][nt][0]), to_tf32(acc[mt][nt][1]));
                *(uint2*)(Cp1 + nt * 8 + 2 * c) =
                    make_uint2(to_tf32(acc[mt][nt][2]), to_tf32(acc[mt][nt][3]));
            } else {
                *(float2*)(Cp0 + nt * 8 + 2 * c) =
                    make_float2(acc[mt][nt][0], acc[mt][nt][1]);
                *(float2*)(Cp1 + nt * 8 + 2 * c) =
                    make_float2(acc[mt][nt][2], acc[mt][nt][3]);
            }
        }
    }
}

// ---------------------------------------------------------------------------
// QKV projections (grid.z = 3): tf32 GEMM, tf32-rounded outputs.
// ---------------------------------------------------------------------------
__global__ __launch_bounds__(256) void gemm_qkv_tf32(
    const float* __restrict__ A0, const float* __restrict__ A1,
    const float* __restrict__ A2,
    const float* __restrict__ W0, const float* __restrict__ W1,
    const float* __restrict__ W2,
    float* __restrict__ C0, float* __restrict__ C1, float* __restrict__ C2)
{
    __shared__ u32 As[128 * LDA];
    __shared__ u32 Bs[32 * LDB];

    const float* A; const float* Bw; float* C;
    if (blockIdx.z == 0)      { A = A0; Bw = W0; C = C0; }
    else if (blockIdx.z == 1) { A = A1; Bw = W1; C = C1; }
    else                      { A = A2; Bw = W2; C = C2; }
    gemm_tf32_body<true>(A, Bw, C, As, Bs);
}

// ---------------------------------------------------------------------------
// Wo projection: tf32 GEMM, fp32 output (verified rel_err 7.24e-4).
// ---------------------------------------------------------------------------
__global__ __launch_bounds__(256) void gemm_wo_tf32(
    const float* __restrict__ A, const float* __restrict__ Bw,
    float* __restrict__ C)
{
    __shared__ u32 As[128 * LDA];
    __shared__ u32 Bs[32 * LDB];
    gemm_tf32_body<false>(A, Bw, C, As, Bs);
}

// ---------------------------------------------------------------------------
// Flash attention v12 (measured as part of the 1062.9us build):
//  - tf32 mma, Bq=128, 256 threads = 8 warps, warp tile m16 x n64
//  - Q fragments in registers; permuted K -> S accumulators ARE PV A-fragments
//  - mask from pre-packed bits; cp.async double-buffered K/V
//  - single barrier per k-tile (wait -> sync -> issue next -> compute)
// smem: 2*K[64][68] + 2*V[64][72] = 71680 B -> 2 CTAs/SM, 16 warps/SM.
// ---------------------------------------------------------------------------
#define LDK 68
#define LDV 72
#define KBW  (64 * LDK)
#define VBW  (64 * LDV)
#define KOFF 0
#define VOFF (2 * KBW)
#define FSMEM ((2 * KBW + 2 * VBW) * 4)   // 71680

__global__ void __launch_bounds__(256, 2) flash_attn(
    const float* __restrict__ Q, const float* __restrict__ K,
    const float* __restrict__ V, float* __restrict__ O)
{
    extern __shared__ u32 dsm[];
    const u32 sbase = (u32)__cvta_generic_to_shared(dsm);

    const int tid  = threadIdx.x;
    const int lane = tid & 31;
    const int w    = tid >> 5;       // warp 0..7 -> q rows [16w, 16w+16)
    const int g    = lane >> 2;
    const int c    = lane & 3;
    const int q0 = blockIdx.x * 128;
    const int h  = blockIdx.y;
    const int b  = blockIdx.z;

    // K/V coop load: 64 rows, 4 threads per row (16 floats each)
    const int r2 = tid >> 2;
    const int qt = (tid & 3) * 16;
    const int prow = (r2 & 56) | (((r2 & 3) << 1) | ((r2 & 7) >> 2));

    const float* ksrc0 = K + ((size_t)(b * Ss + r2)) * HDv + h * 64 + qt;
    const float* vsrc0 = V + ((size_t)(b * Ss + r2)) * HDv + h * 64 + qt;
    const u32 kdst0 = sbase + (KOFF + prow * LDK + qt) * 4;
    const u32 vdst0 = sbase + (VOFF + r2 * LDV + qt) * 4;

    // prologue: issue K/V tile 0 into buffer 0
#pragma unroll
    for (int j = 0; j < 4; ++j) {
        cpa16(kdst0 + 16 * j, ksrc0 + 4 * j);
        cpa16(vdst0 + 16 * j, vsrc0 + 4 * j);
    }
    cpa_commit();

    // Q fragments -> registers (Q already tf32-valued from projection epilogue)
    u32 qf[8][4];
    {
        const u32* q0p = (const u32*)(Q + (size_t)(b * Ss + q0 + 16 * w + g) * HDv + h * 64);
        const u32* q1p = q0p + 8 * HDv;
#pragma unroll
        for (int ks = 0; ks < 8; ++ks) {
            qf[ks][0] = q0p[ks * 8 + c];
            qf[ks][1] = q1p[ks * 8 + c];
            qf[ks][2] = q0p[ks * 8 + c + 4];
            qf[ks][3] = q1p[ks * 8 + c + 4];
        }
    }

    float m_[2], l_[2];
    float o[8][4];
    m_[0] = m_[1] = -CUDART_INF_F;
    l_[0] = l_[1] = 0.f;
#pragma unroll
    for (int nt = 0; nt < 8; ++nt)
#pragma unroll
        for (int j = 0; j < 4; ++j) o[nt][j] = 0.f;

    // packed-mask word bases (Ss/32 = 128 words per q-row)
    const size_t mw0 = ((size_t)((b * Hh + h) * Ss + q0 + 16 * w + g)) * 128;
    const size_t mw1 = mw0 + (size_t)8 * 128;

    for (int it = 0; it < Ss / 64; ++it) {
        const int buf = it & 1;

        // mask words for this tile (independent loads, issued before the wait)
        u32 mwa0 = Mpg[mw0 + it * 2], mwa1 = Mpg[mw0 + it * 2 + 1];
        u32 mwb0 = Mpg[mw1 + it * 2], mwb1 = Mpg[mw1 + it * 2 + 1];

        cpa_wait0();       // tile it landed (issued one compute-phase ago)
        __syncthreads();   // visibility; also: all warps done computing it-1

        // issue tile it+1 into the other buffer (safe: barrier above)
        if (it + 1 < Ss / 64) {
            const float* kp = ksrc0 + (size_t)(it + 1) * 64 * HDv;
            const float* vp = vsrc0 + (size_t)(it + 1) * 64 * HDv;
            const u32 kd = kdst0 + (buf ^ 1) * KBW * 4;
            const u32 vd = vdst0 + (buf ^ 1) * VBW * 4;
#pragma unroll
            for (int j = 0; j < 4; ++j) {
                cpa16(kd + 16 * j, kp + 4 * j);
                cpa16(vd + 16 * j, vp + 4 * j);
            }
            cpa_commit();
        }

        const u32* Kc = dsm + KOFF + buf * KBW;
        const u32* Vc = dsm + VOFF + buf * VBW;

        // ---- S = Q K^T (K columns in permuted slot order) ----
        float s[8][4];
#pragma unroll
        for (int nt = 0; nt < 8; ++nt)
#pragma unroll
            for (int j = 0; j < 4; ++j) s[nt][j] = 0.f;

#pragma unroll
        for (int ks = 0; ks < 8; ++ks) {
#pragma unroll
            for (int nt = 0; nt < 8; ++nt) {
                u32 b0 = Kc[(nt * 8 + g) * LDK + ks * 8 + c];
                u32 b1 = Kc[(nt * 8 + g) * LDK + ks * 8 + c + 4];
                mma_tf32(s[nt][0], s[nt][1], s[nt][2], s[nt][3],
                         qf[ks][0], qf[ks][1], qf[ks][2], qf[ks][3], b0, b1);
            }
        }

        // ---- online softmax; P (tf32-rounded) stays in s[] ----
#pragma unroll
        for (int sb = 0; sb < 2; ++sb) {
            const int j0 = 2 * sb, j1 = 2 * sb + 1;
            const u32 wa = sb ? mwb0 : mwa0;   // cols [it*64, +32)
            const u32 wb = sb ? mwb1 : mwa1;   // cols [it*64+32, +32)
            float mt_ = -CUDART_INF_F;
#pragma unroll
            for (int nt = 0; nt < 8; ++nt) {
                const u32 word = (nt < 4) ? wa : wb;
                const int sh = ((nt & 3) * 8) + c;
                s[nt][j0] = ((word >> sh) & 1u)       ? -1e10f : s[nt][j0] * 0.125f;
                s[nt][j1] = ((word >> (sh + 4)) & 1u) ? -1e10f : s[nt][j1] * 0.125f;
                mt_ = fmaxf(mt_, fmaxf(s[nt][j0], s[nt][j1]));
            }
            mt_ = fmaxf(mt_, __shfl_xor_sync(0xffffffffu, mt_, 1));
            mt_ = fmaxf(mt_, __shfl_xor_sync(0xffffffffu, mt_, 2));
            float mnew = fmaxf(m_[sb], mt_);
            float corr = __expf(m_[sb] - mnew);
            m_[sb] = mnew;
            float rs = 0.f;
#pragma unroll
            for (int nt = 0; nt < 8; ++nt) {
                float p0 = __uint_as_float(to_tf32(__expf(s[nt][j0] - mnew)));
                float p1 = __uint_as_float(to_tf32(__expf(s[nt][j1] - mnew)));
                rs += p0 + p1;
                s[nt][j0] = p0;
                s[nt][j1] = p1;
                o[nt][j0] *= corr;
                o[nt][j1] *= corr;
            }
            rs += __shfl_xor_sync(0xffffffffu, rs, 1);
            rs += __shfl_xor_sync(0xffffffffu, rs, 2);
            l_[sb] = l_[sb] * corr + rs;
        }

        // ---- O += P V : A-fragments straight from s[] ----
#pragma unroll
        for (int kc = 0; kc < 8; ++kc) {
#pragma unroll
            for (int nt = 0; nt < 8; ++nt) {
                u32 b0 = Vc[(kc * 8 + c)     * LDV + nt * 8 + g];
                u32 b1 = Vc[(kc * 8 + c + 4) * LDV + nt * 8 + g];
                mma_tf32(o[nt][0], o[nt][1], o[nt][2], o[nt][3],
                         __float_as_uint(s[kc][0]), __float_as_uint(s[kc][2]),
                         __float_as_uint(s[kc][1]), __float_as_uint(s[kc][3]),
                         b0, b1);
            }
        }
    }

    // normalize + write
    const float inv0 = 1.f / l_[0];
    const float inv1 = 1.f / l_[1];
    float* op0 = O + (size_t)(b * Ss + q0 + 16 * w + g) * HDv + h * 64;
    float* op1 = op0 + (size_t)8 * HDv;
#pragma unroll
    for (int nt = 0; nt < 8; ++nt) {
        *(float2*)(op0 + nt * 8 + 2 * c) = make_float2(o[nt][0] * inv0, o[nt][1] * inv0);
        *(float2*)(op1 + nt * 8 + 2 * c) = make_float2(o[nt][2] * inv1, o[nt][3] * inv1);
    }
}

// ---------------------------------------------------------------------------
// Launch: 4 separate kernels, each with its own optimal resource footprint.
// ---------------------------------------------------------------------------
extern "C" void kernel_launch(void* const* d_in, const int* in_sizes, int n_in,
                              void* d_out, int out_size)
{
    (void)in_sizes; (void)n_in; (void)out_size;
    const float* queries = (const float*)d_in[0];
    const float* keys    = (const float*)d_in[1];
    const float* values  = (const float*)d_in[2];
    const int*   mask    = (const int*)d_in[3];
    const float* Wq = (const float*)d_in[4];
    const float* Wk = (const float*)d_in[5];
    const float* Wv = (const float*)d_in[6];
    const float* Wo = (const float*)d_in[7];

    void *qp, *kp, *vp, *op;
    cudaGetSymbolAddress(&qp, Qg);
    cudaGetSymbolAddress(&kp, Kg);
    cudaGetSymbolAddress(&vp, Vg);
    cudaGetSymbolAddress(&op, Og);

    cudaFuncSetAttribute(flash_attn,
                         cudaFuncAttributeMaxDynamicSharedMemorySize, FSMEM);

    pack_mask<<<1024, 256>>>(mask);

    gemm_qkv_tf32<<<dim3(4, 64, 3), 256>>>(queries, keys, values, Wq, Wk, Wv,
                                           (float*)qp, (float*)kp, (float*)vp);

    flash_attn<<<dim3(Ss / 128, Hh, Bb), 256, FSMEM>>>(
        (const float*)qp, (const float*)kp, (const float*)vp, (float*)op);

    gemm_wo_tf32<<<dim3(4, 64), 256>>>((const float*)op, Wo, (float*)d_out);
}